// round 2
// baseline (speedup 1.0000x reference)
#include <cuda_runtime.h>

using u64 = unsigned long long;
#define DEVFN __device__ __forceinline__

constexpr int    N_ENT   = 100000;
constexpr int    NNZv    = 1600000;
constexpr float  EPSv    = 1e-5f;
constexpr float  INV_NNZ = 1.0f / 1600000.0f;
constexpr int    GSQ_SLOTS = 1024;

// ------------- scratch arena (static __device__, no runtime allocs) ---------
constexpr size_t SZ_BUF  = (size_t)N_ENT * 64;
constexpr size_t O_R0    = 0;
constexpr size_t O_R1    = O_R0 + SZ_BUF;
constexpr size_t O_C0    = O_R1 + SZ_BUF;
constexpr size_t O_C1    = O_C0 + SZ_BUF;
constexpr size_t O_A     = O_C1 + SZ_BUF;
constexpr size_t O_B     = O_A  + SZ_BUF;
constexpr size_t O_O1    = O_B  + SZ_BUF;               // NNZ*32
constexpr size_t O_O2    = O_O1 + (size_t)NNZv * 32;    // NNZ*64
constexpr size_t O_CNTR  = O_O2 + (size_t)NNZv * 64;
constexpr size_t O_CNTC  = O_CNTR + N_ENT;
constexpr size_t O_GSQ   = O_CNTC + N_ENT;              // 1024*64
constexpr size_t O_GSUM  = O_GSQ + GSQ_SLOTS * 64;
constexpr size_t O_S     = O_GSUM + 64;
constexpr size_t O_T     = O_S + 64;
constexpr size_t O_CONST = O_T + 64;
constexpr size_t O_WEFF  = O_CONST + 64;                // 2*64*64
constexpr size_t O_G     = O_WEFF + 8192;               // 32*16
constexpr size_t O_CV    = O_G + 512;
constexpr size_t SCRATCH_TOTAL = O_CV + 64;

__device__ __align__(16) float g_scratch[SCRATCH_TOTAL];

// ------------- packed f32x2 + vector-red helpers ----------------------------
DEVFN void fma2(u64& d, u64 a, u64 b) {
    asm("fma.rn.f32x2 %0, %1, %2, %0;" : "+l"(d) : "l"(a), "l"(b));
}
DEVFN u64 pack2(float x, float y) {
    u64 u; asm("mov.b64 %0, {%1, %2};" : "=l"(u) : "f"(x), "f"(y)); return u;
}
DEVFN u64 splat2(float x) { return pack2(x, x); }
DEVFN float2 unpack2(u64 u) {
    float2 v; asm("mov.b64 {%0, %1}, %2;" : "=f"(v.x), "=f"(v.y) : "l"(u)); return v;
}
DEVFN void redv4(float* p, float4 v) {
    asm volatile("red.global.add.v4.f32 [%0], {%1, %2, %3, %4};"
                 :: "l"(p), "f"(v.x), "f"(v.y), "f"(v.z), "f"(v.w) : "memory");
}
DEVFN void red1(float* p, float v) {
    asm volatile("red.global.add.f32 [%0], %1;" :: "l"(p), "f"(v) : "memory");
}
DEVFN float lane4(float4 v, int s) {
    return (s == 0) ? v.x : (s == 1) ? v.y : (s == 2) ? v.z : v.w;
}

template<int COUT>
DEVFN void accum_pair(u64* acc, const float* WxRow, const float* WyRow, float x, float y) {
    u64 x2 = splat2(x), y2 = splat2(y);
    const u64* w0 = reinterpret_cast<const u64*>(WxRow);
    const u64* w1 = reinterpret_cast<const u64*>(WyRow);
#pragma unroll
    for (int c = 0; c < COUT / 2; ++c) fma2(acc[c], x2, w0[c]);
#pragma unroll
    for (int c = 0; c < COUT / 2; ++c) fma2(acc[c], y2, w1[c]);
}
template<int COUT>
DEVFN void accum_one(u64* acc, const float* WRow, float x) {
    u64 x2 = splat2(x);
    const u64* w0 = reinterpret_cast<const u64*>(WRow);
#pragma unroll
    for (int c = 0; c < COUT / 2; ++c) fma2(acc[c], x2, w0[c]);
}

// ------------- zeroing kernel (no memset nodes) -----------------------------
__global__ void k_zero(float4* p, int n4) {
    int i = blockIdx.x * 256 + threadIdx.x;
    int step = gridDim.x * 256;
    for (; i < n4; i += step) p[i] = make_float4(0.f, 0.f, 0.f, 0.f);
}

// ------------- pass 0: counts + segment sums of raw input -------------------
__global__ void __launch_bounds__(256)
k_sum_input(const float* __restrict__ vals, const int* __restrict__ row,
            const int* __restrict__ col, float* rsum, float* csum,
            float* cntR, float* cntC) {
    int j = blockIdx.x * 256 + threadIdx.x;
    if (j >= NNZv) return;
    int r = row[j], c = col[j];
    red1(cntR + r, 1.0f);
    red1(cntC + c, 1.0f);
    const float4* v4 = reinterpret_cast<const float4*>(vals + (size_t)j * 16);
#pragma unroll
    for (int q = 0; q < 4; ++q) {
        float4 v = v4[q];
        redv4(rsum + (size_t)r * 16 + 4 * q, v);
        redv4(csum + (size_t)c * 16 + 4 * q, v);
    }
}

// ------------- gsum[c] = sum_i rowsum[i][c] ---------------------------------
template<int COUT>
__global__ void __launch_bounds__(256)
k_reduce(const float* __restrict__ rs, float* gsum) {
    constexpr int Q = COUT / 4;
    int tg = blockIdx.x * 256 + threadIdx.x;
    int q = tg % Q, i0 = tg / Q;
    int step = (gridDim.x * 256) / Q;
    float4 p = make_float4(0.f, 0.f, 0.f, 0.f);
    const float4* rs4 = reinterpret_cast<const float4*>(rs);
    for (int i = i0; i < N_ENT; i += step) {
        float4 x = rs4[(size_t)i * Q + q];
        p.x += x.x; p.y += x.y; p.z += x.z; p.w += x.w;
    }
    redv4(gsum + 4 * q, p);
}

// ------------- per-channel norm stats ---------------------------------------
template<int CN>
__global__ void k_stats(const float* __restrict__ gsum, const float* __restrict__ gsq,
                        float* s, float* t) {
    int c = threadIdx.x;
    if (c >= CN) return;
    float sq = 0.f;
    for (int k = 0; k < GSQ_SLOTS; ++k) sq += gsq[(size_t)k * CN + c];
    float m   = gsum[c] * INV_NNZ;
    float var = sq * INV_NNZ - m * m;
    float sc  = rsqrtf(var + EPSv);
    s[c] = sc;
    t[c] = -m * sc;
}
__global__ void k_stats_ident(float* s, float* t) {
    s[threadIdx.x] = 1.0f; t[threadIdx.x] = 0.0f;
}

// ------------- fold norm into next layer weights ----------------------------
template<int CIN, int COUT>
__global__ void k_prep(const float* __restrict__ W, const float* __restrict__ b,
                       const float* __restrict__ gsum, const float* __restrict__ s,
                       const float* __restrict__ t, float* Weff, float* constv) {
    int tid = threadIdx.x;
    for (int i = tid; i < 2 * CIN * COUT; i += blockDim.x) {
        int k = (i % (CIN * COUT)) / COUT;
        Weff[i] = s[k] * W[i];
    }
    if (tid < COUT) {
        float acc = b[tid];
        for (int k = 0; k < CIN; ++k) {
            float tk  = t[k];
            float tmt = fmaf(gsum[k] * INV_NNZ, s[k], tk);  // true global-mean feature
            acc += tk * (W[k * COUT + tid] + W[CIN * COUT + k * COUT + tid])
                 + tmt * W[6 * CIN * COUT + k * COUT + tid];
        }
        constv[tid] = acc;
    }
}

// ------------- per-entity A/B precompute (ops 2..5) -------------------------
// A[i] = rm[i]@W2 + cm[i]@W4   (gathered via row index)
// B[i] = rm[i]@W3 + cm[i]@W5   (gathered via col index)
template<int CIN, int COUT>
__global__ void __launch_bounds__(256)
k_entity(const float* __restrict__ rs, const float* __restrict__ cs,
         const float* __restrict__ cntR, const float* __restrict__ cntC,
         const float* __restrict__ sv, const float* __restrict__ tv,
         const float* __restrict__ W, float* __restrict__ Ab, float* __restrict__ Bb) {
    __shared__ __align__(16) float sW[4 * CIN * COUT];
    __shared__ float ss[CIN], st[CIN];
    int tid = threadIdx.x;
    for (int i = tid; i < 4 * CIN * COUT; i += 256) sW[i] = W[2 * CIN * COUT + i];
    if (tid < CIN) { ss[tid] = sv[tid]; st[tid] = tv[tid]; }
    __syncthreads();

    int gid = blockIdx.x * 256 + tid;
    int i = gid >> 1, half = gid & 1;
    if (i >= N_ENT) return;

    float cr = cntR[i], cc = cntC[i];
    float ir = cr > 0.f ? 1.f / cr : 0.f;
    float ic = cc > 0.f ? 1.f / cc : 0.f;

    u64 acc[COUT / 2];
#pragma unroll
    for (int q = 0; q < COUT / 2; ++q) acc[q] = 0ull;

    const float* Wa = sW + (size_t)half * CIN * COUT;        // W2 / W3
    const float* Wb = sW + (size_t)(2 + half) * CIN * COUT;  // W4 / W5

    const float4* r4 = reinterpret_cast<const float4*>(rs + (size_t)i * CIN);
    const float4* c4 = reinterpret_cast<const float4*>(cs + (size_t)i * CIN);
    for (int k4 = 0; k4 < CIN / 4; ++k4) {
        float4 rv = r4[k4], cv = c4[k4];
#pragma unroll
        for (int s4 = 0; s4 < 4; ++s4) {
            int k = 4 * k4 + s4;
            float fr = (cr > 0.f) ? fmaf(lane4(rv, s4) * ir, ss[k], st[k]) : 0.f;
            float fc = (cc > 0.f) ? fmaf(lane4(cv, s4) * ic, ss[k], st[k]) : 0.f;
            accum_pair<COUT>(acc, Wa + k * COUT, Wb + k * COUT, fr, fc);
        }
    }
    float* dst = (half ? Bb : Ab) + (size_t)i * COUT;
    float4* d4 = reinterpret_cast<float4*>(dst);
#pragma unroll
    for (int q = 0; q < COUT / 4; ++q) {
        float2 lo = unpack2(acc[2 * q]), hi = unpack2(acc[2 * q + 1]);
        d4[q] = make_float4(lo.x, lo.y, hi.x, hi.y);
    }
}

// ------------- main per-nnz kernel (ops 0,1 + relu + fused reductions) ------
template<int CIN, int COUT, bool STORE_O, bool DO_COL>
__global__ void __launch_bounds__(256)
k_main(const float* __restrict__ vin, const int* __restrict__ row,
       const int* __restrict__ col, const int* __restrict__ perm,
       const float* __restrict__ Weff, const float* __restrict__ constv,
       const float* __restrict__ Ab, const float* __restrict__ Bb,
       float* __restrict__ o, float* __restrict__ rsum,
       float* __restrict__ csum, float* __restrict__ gsq) {
    __shared__ __align__(16) float sW[2 * CIN * COUT];
    __shared__ float sC[COUT];
    int tid = threadIdx.x;
    for (int i = tid; i < 2 * CIN * COUT; i += 256) sW[i] = Weff[i];
    if (tid < COUT) sC[tid] = constv[tid];
    __syncthreads();

    int j = blockIdx.x * 256 + tid;
    if (j >= NNZv) return;
    int r = row[j], c = col[j], p = perm[j];

    u64 acc[COUT / 2];
    const float4* A4 = reinterpret_cast<const float4*>(Ab + (size_t)r * COUT);
    const float4* B4 = reinterpret_cast<const float4*>(Bb + (size_t)c * COUT);
#pragma unroll
    for (int q = 0; q < COUT / 4; ++q) {
        float4 a = __ldg(A4 + q), b = __ldg(B4 + q);
        acc[2 * q]     = pack2(a.x + b.x + sC[4 * q],     a.y + b.y + sC[4 * q + 1]);
        acc[2 * q + 1] = pack2(a.z + b.z + sC[4 * q + 2], a.w + b.w + sC[4 * q + 3]);
    }

    const float4* v4 = reinterpret_cast<const float4*>(vin + (size_t)j * CIN);
    const float4* g4 = reinterpret_cast<const float4*>(vin + (size_t)p * CIN);
    for (int k4 = 0; k4 < CIN / 4; ++k4) {
        float4 xv = v4[k4];
        float4 xg = g4[k4];
#pragma unroll
        for (int s4 = 0; s4 < 4; ++s4) {
            int k = 4 * k4 + s4;
            accum_pair<COUT>(acc, sW + k * COUT, sW + CIN * COUT + k * COUT,
                             lane4(xv, s4), lane4(xg, s4));
        }
    }

    float4* o4 = STORE_O ? reinterpret_cast<float4*>(o + (size_t)j * COUT) : nullptr;
    float* gq = gsq + (size_t)(((blockIdx.x & 3) << 8) | tid) * COUT;
#pragma unroll
    for (int q = 0; q < COUT / 4; ++q) {
        float2 lo = unpack2(acc[2 * q]), hi = unpack2(acc[2 * q + 1]);
        float4 ov = make_float4(fmaxf(lo.x, 0.f), fmaxf(lo.y, 0.f),
                                fmaxf(hi.x, 0.f), fmaxf(hi.y, 0.f));
        if (STORE_O) o4[q] = ov;
        redv4(rsum + (size_t)r * COUT + 4 * q, ov);
        if (DO_COL) redv4(csum + (size_t)c * COUT + 4 * q, ov);
        redv4(gq + 4 * q, make_float4(ov.x * ov.x, ov.y * ov.y, ov.z * ov.z, ov.w * ov.w));
    }
}

// ------------- head: G = Wp@Wl, cvec = bp@Wl + bl ---------------------------
__global__ void k_head_prep(const float* __restrict__ Wp, const float* __restrict__ bp,
                            const float* __restrict__ Wl, const float* __restrict__ bl,
                            float* G, float* cvec) {
    int tid = threadIdx.x;
    if (tid < 32 * 16) {
        int kin = tid >> 4, c = tid & 15;
        float g = 0.f;
        for (int e = 0; e < 16; ++e) g += Wp[kin * 16 + e] * Wl[e * 16 + c];
        G[tid] = g;
    }
    if (tid < 16) {
        float cv = bl[tid];
        for (int e = 0; e < 16; ++e) cv += bp[e] * Wl[e * 16 + tid];
        cvec[tid] = cv;
    }
}

__global__ void __launch_bounds__(256)
k_final(const float* __restrict__ rs, const float* __restrict__ cntR,
        const float* __restrict__ sv, const float* __restrict__ tv,
        const float* __restrict__ G, const float* __restrict__ cvec,
        float* __restrict__ out) {
    __shared__ __align__(16) float sG[32 * 16];
    __shared__ float scv[16], ss[32], st[32];
    int tid = threadIdx.x;
    for (int i = tid; i < 512; i += 256) sG[i] = G[i];
    if (tid < 16) scv[tid] = cvec[tid];
    if (tid < 32) { ss[tid] = sv[tid]; st[tid] = tv[tid]; }
    __syncthreads();

    int i = blockIdx.x * 256 + tid;
    if (i >= N_ENT) return;
    float cr = cntR[i];
    float ir = cr > 0.f ? 1.f / cr : 0.f;

    u64 acc[8];
#pragma unroll
    for (int q = 0; q < 8; ++q) acc[q] = pack2(scv[2 * q], scv[2 * q + 1]);

    const float4* r4 = reinterpret_cast<const float4*>(rs + (size_t)i * 32);
    for (int k4 = 0; k4 < 8; ++k4) {
        float4 rv = r4[k4];
#pragma unroll
        for (int s4 = 0; s4 < 4; ++s4) {
            int k = 4 * k4 + s4;
            float f = (cr > 0.f) ? fmaf(lane4(rv, s4) * ir, ss[k], st[k]) : 0.f;
            accum_one<16>(acc, sG + k * 16, f);
        }
    }
    float4* d4 = reinterpret_cast<float4*>(out + (size_t)i * 16);
#pragma unroll
    for (int q = 0; q < 4; ++q) {
        float2 lo = unpack2(acc[2 * q]), hi = unpack2(acc[2 * q + 1]);
        d4[q] = make_float4(lo.x, lo.y, hi.x, hi.y);
    }
}

// ------------- host orchestration -------------------------------------------
extern "C" void kernel_launch(void* const* d_in, const int* in_sizes, int n_in,
                              void* d_out, int out_size) {
    const float* values = (const float*)d_in[0];
    const int*   row    = (const int*)d_in[1];
    const int*   col    = (const int*)d_in[2];
    const int*   perm   = (const int*)d_in[3];
    const float* W1 = (const float*)d_in[4];  const float* b1 = (const float*)d_in[5];
    const float* W2 = (const float*)d_in[6];  const float* b2 = (const float*)d_in[7];
    const float* W3 = (const float*)d_in[8];  const float* b3 = (const float*)d_in[9];
    const float* Wp = (const float*)d_in[10]; const float* bp = (const float*)d_in[11];
    const float* Wl = (const float*)d_in[12]; const float* bl = (const float*)d_in[13];
    float* out = (float*)d_out;

    float* S = nullptr;
    cudaGetSymbolAddress((void**)&S, g_scratch);

    float *R0 = S + O_R0, *R1 = S + O_R1, *C0 = S + O_C0, *C1 = S + O_C1;
    float *A  = S + O_A,  *B  = S + O_B;
    float *o1 = S + O_O1, *o2 = S + O_O2;
    float *cntR = S + O_CNTR, *cntC = S + O_CNTC;
    float *gsq = S + O_GSQ, *gsum = S + O_GSUM;
    float *sb = S + O_S, *tb = S + O_T, *cvv = S + O_CONST, *Weff = S + O_WEFF;
    float *G = S + O_G, *cvec = S + O_CV;

    auto zero = [](float* p, size_t n) {
        int n4 = (int)(n / 4);
        int grid = (n4 + 255) / 256; if (grid > 2048) grid = 2048;
        k_zero<<<grid, 256>>>((float4*)p, n4);
    };
    constexpr int GM = (NNZv + 255) / 256;   // 6250
    constexpr int GE = (2 * N_ENT + 255) / 256;

    // ---- layer 1 (16 -> 32), s=1, t=0 ----
    zero(R0, 4 * SZ_BUF);                    // R0,R1,C0,C1
    zero(cntR, 2 * N_ENT);                   // cntR,cntC
    zero(gsq, GSQ_SLOTS * 64 + 64);          // gsq + gsum
    k_sum_input<<<GM, 256>>>(values, row, col, R0, C0, cntR, cntC);
    k_reduce<16><<<64, 256>>>(R0, gsum);
    k_stats_ident<<<1, 64>>>(sb, tb);
    k_prep<16, 32><<<1, 256>>>(W1, b1, gsum, sb, tb, Weff, cvv);
    k_entity<16, 32><<<GE, 256>>>(R0, C0, cntR, cntC, sb, tb, W1, A, B);
    k_main<16, 32, true, true><<<GM, 256>>>(values, row, col, perm, Weff, cvv,
                                            A, B, o1, R1, C1, gsq);
    // ---- layer 2 (32 -> 64) ----
    zero(gsum, 64);
    k_reduce<32><<<64, 256>>>(R1, gsum);
    k_stats<32><<<1, 64>>>(gsum, gsq, sb, tb);
    k_prep<32, 64><<<1, 256>>>(W2, b2, gsum, sb, tb, Weff, cvv);
    k_entity<32, 64><<<GE, 256>>>(R1, C1, cntR, cntC, sb, tb, W2, A, B);
    zero(R0, SZ_BUF); zero(C0, SZ_BUF); zero(gsq, GSQ_SLOTS * 64);
    k_main<32, 64, true, true><<<GM, 256>>>(o1, row, col, perm, Weff, cvv,
                                            A, B, o2, R0, C0, gsq);
    // ---- layer 3 (64 -> 32), output not materialized ----
    zero(gsum, 64);
    k_reduce<64><<<64, 256>>>(R0, gsum);
    k_stats<64><<<1, 64>>>(gsum, gsq, sb, tb);
    k_prep<64, 32><<<1, 256>>>(W3, b3, gsum, sb, tb, Weff, cvv);
    k_entity<64, 32><<<GE, 256>>>(R0, C0, cntR, cntC, sb, tb, W3, A, B);
    zero(R1, SZ_BUF); zero(gsq, GSQ_SLOTS * 64);
    k_main<64, 32, false, false><<<GM, 256>>>(o2, row, col, perm, Weff, cvv,
                                              A, B, nullptr, R1, nullptr, gsq);
    // ---- head ----
    zero(gsum, 64);
    k_reduce<32><<<64, 256>>>(R1, gsum);
    k_stats<32><<<1, 64>>>(gsum, gsq, sb, tb);
    k_head_prep<<<1, 512>>>(Wp, bp, Wl, bl, G, cvec);
    k_final<<<(N_ENT + 255) / 256, 256>>>(R1, cntR, sb, tb, G, cvec, out);
}

// round 3
// speedup vs baseline: 1.1346x; 1.1346x over previous
#include <cuda_runtime.h>

using u64 = unsigned long long;
#define DEVFN __device__ __forceinline__

constexpr int    N_ENT   = 100000;
constexpr int    NNZv    = 1600000;
constexpr int    HALFv   = NNZv / 2;
constexpr float  EPSv    = 1e-5f;
constexpr float  INV_NNZ = 1.0f / 1600000.0f;
constexpr int    GSQ_SLOTS = 1024;

// ------------- scratch arena (static __device__, no runtime allocs) ---------
constexpr size_t SZ_BUF  = (size_t)N_ENT * 64;
constexpr size_t O_R0    = 0;
constexpr size_t O_R1    = O_R0 + SZ_BUF;
constexpr size_t O_C0    = O_R1 + SZ_BUF;
constexpr size_t O_C1    = O_C0 + SZ_BUF;
constexpr size_t O_A     = O_C1 + SZ_BUF;
constexpr size_t O_B     = O_A  + SZ_BUF;
constexpr size_t O_O1    = O_B  + SZ_BUF;               // NNZ*32
constexpr size_t O_O2    = O_O1 + (size_t)NNZv * 32;    // NNZ*64
constexpr size_t O_CNTR  = O_O2 + (size_t)NNZv * 64;
constexpr size_t O_GSQ   = O_CNTR + N_ENT;              // 1024*64
constexpr size_t O_GSUM  = O_GSQ + GSQ_SLOTS * 64;
constexpr size_t O_S     = O_GSUM + 64;
constexpr size_t O_T     = O_S + 64;
constexpr size_t O_CONST = O_T + 64;
constexpr size_t O_WEFF  = O_CONST + 64;                // 2*64*64
constexpr size_t O_G     = O_WEFF + 8192;               // 32*16
constexpr size_t O_CV    = O_G + 512;
constexpr size_t SCRATCH_TOTAL = O_CV + 64;

__device__ __align__(16) float g_scratch[SCRATCH_TOTAL];

// ------------- packed f32x2 + vector-red helpers ----------------------------
DEVFN void fma2(u64& d, u64 a, u64 b) {
    asm("fma.rn.f32x2 %0, %1, %2, %0;" : "+l"(d) : "l"(a), "l"(b));
}
DEVFN u64 pack2(float x, float y) {
    u64 u; asm("mov.b64 %0, {%1, %2};" : "=l"(u) : "f"(x), "f"(y)); return u;
}
DEVFN u64 splat2(float x) { return pack2(x, x); }
DEVFN float2 unpack2(u64 u) {
    float2 v; asm("mov.b64 {%0, %1}, %2;" : "=f"(v.x), "=f"(v.y) : "l"(u)); return v;
}
DEVFN void redv4(float* p, float4 v) {
    asm volatile("red.global.add.v4.f32 [%0], {%1, %2, %3, %4};"
                 :: "l"(p), "f"(v.x), "f"(v.y), "f"(v.z), "f"(v.w) : "memory");
}
DEVFN void red1(float* p, float v) {
    asm volatile("red.global.add.f32 [%0], %1;" :: "l"(p), "f"(v) : "memory");
}
DEVFN float lane4(float4 v, int s) {
    return (s == 0) ? v.x : (s == 1) ? v.y : (s == 2) ? v.z : v.w;
}

template<int COUT>
DEVFN void accum_pair(u64* acc, const float* WxRow, const float* WyRow, float x, float y) {
    u64 x2 = splat2(x), y2 = splat2(y);
    const u64* w0 = reinterpret_cast<const u64*>(WxRow);
    const u64* w1 = reinterpret_cast<const u64*>(WyRow);
#pragma unroll
    for (int c = 0; c < COUT / 2; ++c) fma2(acc[c], x2, w0[c]);
#pragma unroll
    for (int c = 0; c < COUT / 2; ++c) fma2(acc[c], y2, w1[c]);
}
template<int COUT>
DEVFN void accum_one(u64* acc, const float* WRow, float x) {
    u64 x2 = splat2(x);
    const u64* w0 = reinterpret_cast<const u64*>(WRow);
#pragma unroll
    for (int c = 0; c < COUT / 2; ++c) fma2(acc[c], x2, w0[c]);
}

// ------------- zeroing kernel (no memset nodes) -----------------------------
__global__ void k_zero(float4* p, int n4) {
    int i = blockIdx.x * 256 + threadIdx.x;
    int step = gridDim.x * 256;
    for (; i < n4; i += step) p[i] = make_float4(0.f, 0.f, 0.f, 0.f);
}

// ------------- pass 0 (paired): counts + segment sums of raw input ----------
__global__ void __launch_bounds__(256)
k_sum_input(const float* __restrict__ vals, const int* __restrict__ row,
            const int* __restrict__ col, const int* __restrict__ perm,
            float* rsum, float* csum, float* cntR) {
    int j = blockIdx.x * 256 + threadIdx.x;
    if (j >= HALFv) return;
    int j2 = perm[j];
    int r = row[j], c = col[j];
    red1(cntR + r, 1.0f);
    red1(cntR + c, 1.0f);
    const float4* v4  = reinterpret_cast<const float4*>(vals + (size_t)j  * 16);
    const float4* w4  = reinterpret_cast<const float4*>(vals + (size_t)j2 * 16);
#pragma unroll
    for (int q = 0; q < 4; ++q) {
        float4 v = v4[q];
        redv4(rsum + (size_t)r * 16 + 4 * q, v);
        redv4(csum + (size_t)c * 16 + 4 * q, v);
        float4 w = w4[q];
        redv4(rsum + (size_t)c * 16 + 4 * q, w);
        redv4(csum + (size_t)r * 16 + 4 * q, w);
    }
}

// ------------- gsum[c] = sum_i rowsum[i][c] ---------------------------------
template<int COUT>
__global__ void __launch_bounds__(256)
k_reduce(const float* __restrict__ rs, float* gsum) {
    constexpr int Q = COUT / 4;
    int tg = blockIdx.x * 256 + threadIdx.x;
    int q = tg % Q, i0 = tg / Q;
    int step = (gridDim.x * 256) / Q;
    float4 p = make_float4(0.f, 0.f, 0.f, 0.f);
    const float4* rs4 = reinterpret_cast<const float4*>(rs);
    for (int i = i0; i < N_ENT; i += step) {
        float4 x = rs4[(size_t)i * Q + q];
        p.x += x.x; p.y += x.y; p.z += x.z; p.w += x.w;
    }
    redv4(gsum + 4 * q, p);
}

// ------------- per-channel norm stats ---------------------------------------
template<int CN>
__global__ void k_stats(const float* __restrict__ gsum, const float* __restrict__ gsq,
                        float* s, float* t) {
    int c = threadIdx.x;
    if (c >= CN) return;
    float sq = 0.f;
    for (int k = 0; k < GSQ_SLOTS; ++k) sq += gsq[(size_t)k * CN + c];
    float m   = gsum[c] * INV_NNZ;
    float var = sq * INV_NNZ - m * m;
    float sc  = rsqrtf(var + EPSv);
    s[c] = sc;
    t[c] = -m * sc;
}
__global__ void k_stats_ident(float* s, float* t) {
    s[threadIdx.x] = 1.0f; t[threadIdx.x] = 0.0f;
}

// ------------- fold norm into next layer weights ----------------------------
template<int CIN, int COUT>
__global__ void k_prep(const float* __restrict__ W, const float* __restrict__ b,
                       const float* __restrict__ gsum, const float* __restrict__ s,
                       const float* __restrict__ t, float* Weff, float* constv) {
    int tid = threadIdx.x;
    for (int i = tid; i < 2 * CIN * COUT; i += blockDim.x) {
        int k = (i % (CIN * COUT)) / COUT;
        Weff[i] = s[k] * W[i];
    }
    if (tid < COUT) {
        float acc = b[tid];
        for (int k = 0; k < CIN; ++k) {
            float tk  = t[k];
            float tmt = fmaf(gsum[k] * INV_NNZ, s[k], tk);  // global-mean feature
            acc += tk * (W[k * COUT + tid] + W[CIN * COUT + k * COUT + tid])
                 + tmt * W[6 * CIN * COUT + k * COUT + tid];
        }
        constv[tid] = acc;
    }
}

// ------------- per-entity A/B precompute (ops 2..5) -------------------------
template<int CIN, int COUT>
__global__ void __launch_bounds__(256)
k_entity(const float* __restrict__ rs, const float* __restrict__ cs,
         const float* __restrict__ cntR, const float* __restrict__ cntC,
         const float* __restrict__ sv, const float* __restrict__ tv,
         const float* __restrict__ W, float* __restrict__ Ab, float* __restrict__ Bb) {
    __shared__ __align__(16) float sW[4 * CIN * COUT];
    __shared__ float ss[CIN], st[CIN];
    int tid = threadIdx.x;
    for (int i = tid; i < 4 * CIN * COUT; i += 256) sW[i] = W[2 * CIN * COUT + i];
    if (tid < CIN) { ss[tid] = sv[tid]; st[tid] = tv[tid]; }
    __syncthreads();

    int gid = blockIdx.x * 256 + tid;
    int i = gid >> 1, half = gid & 1;
    if (i >= N_ENT) return;

    float cr = cntR[i], cc = cntC[i];
    float ir = cr > 0.f ? 1.f / cr : 0.f;
    float ic = cc > 0.f ? 1.f / cc : 0.f;

    u64 acc[COUT / 2];
#pragma unroll
    for (int q = 0; q < COUT / 2; ++q) acc[q] = 0ull;

    const float* Wa = sW + (size_t)half * CIN * COUT;        // W2 / W3
    const float* Wb = sW + (size_t)(2 + half) * CIN * COUT;  // W4 / W5

    const float4* r4 = reinterpret_cast<const float4*>(rs + (size_t)i * CIN);
    const float4* c4 = reinterpret_cast<const float4*>(cs + (size_t)i * CIN);
    for (int k4 = 0; k4 < CIN / 4; ++k4) {
        float4 rv = r4[k4], cv = c4[k4];
#pragma unroll
        for (int s4 = 0; s4 < 4; ++s4) {
            int k = 4 * k4 + s4;
            float fr = (cr > 0.f) ? fmaf(lane4(rv, s4) * ir, ss[k], st[k]) : 0.f;
            float fc = (cc > 0.f) ? fmaf(lane4(cv, s4) * ic, ss[k], st[k]) : 0.f;
            accum_pair<COUT>(acc, Wa + k * COUT, Wb + k * COUT, fr, fc);
        }
    }
    float* dst = (half ? Bb : Ab) + (size_t)i * COUT;
    float4* d4 = reinterpret_cast<float4*>(dst);
#pragma unroll
    for (int q = 0; q < COUT / 4; ++q) {
        float2 lo = unpack2(acc[2 * q]), hi = unpack2(acc[2 * q + 1]);
        d4[q] = make_float4(lo.x, lo.y, hi.x, hi.y);
    }
}

// ------------- main paired per-nnz kernel -----------------------------------
// Processes the transpose pair (j, perm[j]) together: both outputs share the
// same two input rows (loaded once) and the same broadcast weight rows.
template<int CIN, int COUT, int ITER, bool STORE_O, bool DO_COL>
__global__ void __launch_bounds__((COUT == 64) ? 128 : 256)
k_mainp(const float* __restrict__ vin, const int* __restrict__ row,
        const int* __restrict__ col, const int* __restrict__ perm,
        const float* __restrict__ Weff, const float* __restrict__ constv,
        const float* __restrict__ Ab, const float* __restrict__ Bb,
        float* __restrict__ o, float* __restrict__ rsum,
        float* __restrict__ csum, float* __restrict__ gsq) {
    constexpr int NT = (COUT == 64) ? 128 : 256;
    __shared__ __align__(16) float sW[2 * CIN * COUT];
    __shared__ float sC[COUT];
    int tid = threadIdx.x;
    for (int i = tid; i < 2 * CIN * COUT; i += NT) sW[i] = Weff[i];
    if (tid < COUT) sC[tid] = constv[tid];
    __syncthreads();

    u64 sq[COUT / 2];
#pragma unroll
    for (int q = 0; q < COUT / 2; ++q) sq[q] = 0ull;

    for (int it = 0; it < ITER; ++it) {
        int j = (blockIdx.x * ITER + it) * NT + tid;
        if (j >= HALFv) break;
        int j2 = perm[j];
        int r = row[j], c = col[j];

        u64 acc0[COUT / 2], acc1[COUT / 2];
        const float4* Ar = reinterpret_cast<const float4*>(Ab + (size_t)r * COUT);
        const float4* Bc = reinterpret_cast<const float4*>(Bb + (size_t)c * COUT);
        const float4* Ac = reinterpret_cast<const float4*>(Ab + (size_t)c * COUT);
        const float4* Br = reinterpret_cast<const float4*>(Bb + (size_t)r * COUT);
#pragma unroll
        for (int q = 0; q < COUT / 4; ++q) {
            float4 a = __ldg(Ar + q), b = __ldg(Bc + q);
            acc0[2 * q]     = pack2(a.x + b.x + sC[4 * q],     a.y + b.y + sC[4 * q + 1]);
            acc0[2 * q + 1] = pack2(a.z + b.z + sC[4 * q + 2], a.w + b.w + sC[4 * q + 3]);
            float4 a2 = __ldg(Ac + q), b2 = __ldg(Br + q);
            acc1[2 * q]     = pack2(a2.x + b2.x + sC[4 * q],     a2.y + b2.y + sC[4 * q + 1]);
            acc1[2 * q + 1] = pack2(a2.z + b2.z + sC[4 * q + 2], a2.w + b2.w + sC[4 * q + 3]);
        }

        const float4* v4 = reinterpret_cast<const float4*>(vin + (size_t)j  * CIN);
        const float4* g4 = reinterpret_cast<const float4*>(vin + (size_t)j2 * CIN);
        for (int k4 = 0; k4 < CIN / 4; ++k4) {
            float4 xv = v4[k4];
            float4 yv = g4[k4];
#pragma unroll
            for (int s4 = 0; s4 < 4; ++s4) {
                int k = 4 * k4 + s4;
                float x = lane4(xv, s4), y = lane4(yv, s4);
                const float* W0 = sW + k * COUT;
                const float* W1 = sW + CIN * COUT + k * COUT;
                accum_pair<COUT>(acc0, W0, W1, x, y);   // h[j]  = x@W0 + y@W1
                accum_pair<COUT>(acc1, W0, W1, y, x);   // h[j2] = y@W0 + x@W1
            }
        }

        float4* o4a = STORE_O ? reinterpret_cast<float4*>(o + (size_t)j  * COUT) : nullptr;
        float4* o4b = STORE_O ? reinterpret_cast<float4*>(o + (size_t)j2 * COUT) : nullptr;
#pragma unroll
        for (int q = 0; q < COUT / 4; ++q) {
            float2 lo0 = unpack2(acc0[2 * q]), hi0 = unpack2(acc0[2 * q + 1]);
            float4 h0 = make_float4(fmaxf(lo0.x, 0.f), fmaxf(lo0.y, 0.f),
                                    fmaxf(hi0.x, 0.f), fmaxf(hi0.y, 0.f));
            float2 lo1 = unpack2(acc1[2 * q]), hi1 = unpack2(acc1[2 * q + 1]);
            float4 h1 = make_float4(fmaxf(lo1.x, 0.f), fmaxf(lo1.y, 0.f),
                                    fmaxf(hi1.x, 0.f), fmaxf(hi1.y, 0.f));
            if (STORE_O) { o4a[q] = h0; o4b[q] = h1; }
            redv4(rsum + (size_t)r * COUT + 4 * q, h0);
            redv4(rsum + (size_t)c * COUT + 4 * q, h1);
            if (DO_COL) {
                redv4(csum + (size_t)c * COUT + 4 * q, h0);
                redv4(csum + (size_t)r * COUT + 4 * q, h1);
            }
            u64 p0 = pack2(h0.x, h0.y), p1 = pack2(h0.z, h0.w);
            u64 p2 = pack2(h1.x, h1.y), p3 = pack2(h1.z, h1.w);
            fma2(sq[2 * q],     p0, p0); fma2(sq[2 * q + 1], p1, p1);
            fma2(sq[2 * q],     p2, p2); fma2(sq[2 * q + 1], p3, p3);
        }
    }

    int slot = (blockIdx.x * NT + tid) & (GSQ_SLOTS - 1);
    float* gq = gsq + (size_t)slot * COUT;
#pragma unroll
    for (int q = 0; q < COUT / 4; ++q) {
        float2 lo = unpack2(sq[2 * q]), hi = unpack2(sq[2 * q + 1]);
        redv4(gq + 4 * q, make_float4(lo.x, lo.y, hi.x, hi.y));
    }
}

// ------------- head: G = Wp@Wl, cvec = bp@Wl + bl ---------------------------
__global__ void k_head_prep(const float* __restrict__ Wp, const float* __restrict__ bp,
                            const float* __restrict__ Wl, const float* __restrict__ bl,
                            float* G, float* cvec) {
    int tid = threadIdx.x;
    if (tid < 32 * 16) {
        int kin = tid >> 4, c = tid & 15;
        float g = 0.f;
        for (int e = 0; e < 16; ++e) g += Wp[kin * 16 + e] * Wl[e * 16 + c];
        G[tid] = g;
    }
    if (tid < 16) {
        float cv = bl[tid];
        for (int e = 0; e < 16; ++e) cv += bp[e] * Wl[e * 16 + tid];
        cvec[tid] = cv;
    }
}

__global__ void __launch_bounds__(256)
k_final(const float* __restrict__ rs, const float* __restrict__ cntR,
        const float* __restrict__ sv, const float* __restrict__ tv,
        const float* __restrict__ G, const float* __restrict__ cvec,
        float* __restrict__ out) {
    __shared__ __align__(16) float sG[32 * 16];
    __shared__ float scv[16], ss[32], st[32];
    int tid = threadIdx.x;
    for (int i = tid; i < 512; i += 256) sG[i] = G[i];
    if (tid < 16) scv[tid] = cvec[tid];
    if (tid < 32) { ss[tid] = sv[tid]; st[tid] = tv[tid]; }
    __syncthreads();

    int i = blockIdx.x * 256 + tid;
    if (i >= N_ENT) return;
    float cr = cntR[i];
    float ir = cr > 0.f ? 1.f / cr : 0.f;

    u64 acc[8];
#pragma unroll
    for (int q = 0; q < 8; ++q) acc[q] = pack2(scv[2 * q], scv[2 * q + 1]);

    const float4* r4 = reinterpret_cast<const float4*>(rs + (size_t)i * 32);
    for (int k4 = 0; k4 < 8; ++k4) {
        float4 rv = r4[k4];
#pragma unroll
        for (int s4 = 0; s4 < 4; ++s4) {
            int k = 4 * k4 + s4;
            float f = (cr > 0.f) ? fmaf(lane4(rv, s4) * ir, ss[k], st[k]) : 0.f;
            accum_one<16>(acc, sG + k * 16, f);
        }
    }
    float4* d4 = reinterpret_cast<float4*>(out + (size_t)i * 16);
#pragma unroll
    for (int q = 0; q < 4; ++q) {
        float2 lo = unpack2(acc[2 * q]), hi = unpack2(acc[2 * q + 1]);
        d4[q] = make_float4(lo.x, lo.y, hi.x, hi.y);
    }
}

// ------------- host orchestration -------------------------------------------
extern "C" void kernel_launch(void* const* d_in, const int* in_sizes, int n_in,
                              void* d_out, int out_size) {
    const float* values = (const float*)d_in[0];
    const int*   row    = (const int*)d_in[1];
    const int*   col    = (const int*)d_in[2];
    const int*   perm   = (const int*)d_in[3];
    const float* W1 = (const float*)d_in[4];  const float* b1 = (const float*)d_in[5];
    const float* W2 = (const float*)d_in[6];  const float* b2 = (const float*)d_in[7];
    const float* W3 = (const float*)d_in[8];  const float* b3 = (const float*)d_in[9];
    const float* Wp = (const float*)d_in[10]; const float* bp = (const float*)d_in[11];
    const float* Wl = (const float*)d_in[12]; const float* bl = (const float*)d_in[13];
    float* out = (float*)d_out;

    float* S = nullptr;
    cudaGetSymbolAddress((void**)&S, g_scratch);

    float *R0 = S + O_R0, *R1 = S + O_R1, *C0 = S + O_C0, *C1 = S + O_C1;
    float *A  = S + O_A,  *B  = S + O_B;
    float *o1 = S + O_O1, *o2 = S + O_O2;
    float *cntR = S + O_CNTR;
    float *gsq = S + O_GSQ, *gsum = S + O_GSUM;
    float *sb = S + O_S, *tb = S + O_T, *cvv = S + O_CONST, *Weff = S + O_WEFF;
    float *G = S + O_G, *cvec = S + O_CV;

    auto zero = [](float* p, size_t n) {
        int n4 = (int)(n / 4);
        int grid = (n4 + 255) / 256; if (grid > 2048) grid = 2048;
        k_zero<<<grid, 256>>>((float4*)p, n4);
    };
    constexpr int GS  = (HALFv + 255) / 256;                 // paired, ITER=1, 256t
    constexpr int GP4 = (HALFv + 256 * 4 - 1) / (256 * 4);   // paired, ITER=4, 256t
    constexpr int GP1 = (HALFv + 127) / 128;                 // paired, ITER=1, 128t
    constexpr int GE  = (2 * N_ENT + 255) / 256;

    // ---- layer 1 (16 -> 32), s=1, t=0 ----
    zero(R0, 4 * SZ_BUF);                    // R0,R1,C0,C1
    zero(cntR, N_ENT);
    zero(gsq, GSQ_SLOTS * 64 + 64);          // gsq + gsum
    k_sum_input<<<GS, 256>>>(values, row, col, perm, R0, C0, cntR);
    k_reduce<16><<<64, 256>>>(R0, gsum);
    k_stats_ident<<<1, 64>>>(sb, tb);
    k_prep<16, 32><<<1, 256>>>(W1, b1, gsum, sb, tb, Weff, cvv);
    k_entity<16, 32><<<GE, 256>>>(R0, C0, cntR, cntR, sb, tb, W1, A, B);
    k_mainp<16, 32, 4, true, true><<<GP4, 256>>>(values, row, col, perm, Weff, cvv,
                                                 A, B, o1, R1, C1, gsq);
    // ---- layer 2 (32 -> 64) ----
    zero(gsum, 64);
    k_reduce<32><<<64, 256>>>(R1, gsum);
    k_stats<32><<<1, 64>>>(gsum, gsq, sb, tb);
    k_prep<32, 64><<<1, 256>>>(W2, b2, gsum, sb, tb, Weff, cvv);
    k_entity<32, 64><<<GE, 256>>>(R1, C1, cntR, cntR, sb, tb, W2, A, B);
    zero(R0, SZ_BUF); zero(C0, SZ_BUF); zero(gsq, GSQ_SLOTS * 64);
    k_mainp<32, 64, 1, true, true><<<GP1, 128>>>(o1, row, col, perm, Weff, cvv,
                                                 A, B, o2, R0, C0, gsq);
    // ---- layer 3 (64 -> 32), output not materialized ----
    zero(gsum, 64);
    k_reduce<64><<<64, 256>>>(R0, gsum);
    k_stats<64><<<1, 64>>>(gsum, gsq, sb, tb);
    k_prep<64, 32><<<1, 256>>>(W3, b3, gsum, sb, tb, Weff, cvv);
    k_entity<64, 32><<<GE, 256>>>(R0, C0, cntR, cntR, sb, tb, W3, A, B);
    zero(R1, SZ_BUF); zero(gsq, GSQ_SLOTS * 64);
    k_mainp<64, 32, 4, false, false><<<GP4, 256>>>(o2, row, col, perm, Weff, cvv,
                                                   A, B, nullptr, R1, nullptr, gsq);
    // ---- head ----
    zero(gsum, 64);
    k_reduce<32><<<64, 256>>>(R1, gsum);
    k_stats<32><<<1, 64>>>(gsum, gsq, sb, tb);
    k_head_prep<<<1, 512>>>(Wp, bp, Wl, bl, G, cvec);
    k_final<<<(N_ENT + 255) / 256, 256>>>(R1, cntR, sb, tb, G, cvec, out);
}

// round 4
// speedup vs baseline: 1.1977x; 1.0556x over previous
#include <cuda_runtime.h>

using u64 = unsigned long long;
#define DEVFN __device__ __forceinline__

constexpr int    N_ENT   = 100000;
constexpr int    NNZv    = 1600000;
constexpr int    HALFv   = NNZv / 2;
constexpr float  EPSv    = 1e-5f;
constexpr float  INV_NNZ = 1.0f / 1600000.0f;
constexpr int    GSQ_SLOTS = 1024;

// ------------- scratch arena (static __device__, no runtime allocs) ---------
constexpr size_t SZ_BUF  = (size_t)N_ENT * 64;
constexpr size_t O_R0    = 0;
constexpr size_t O_R1    = O_R0 + SZ_BUF;
constexpr size_t O_C0    = O_R1 + SZ_BUF;
constexpr size_t O_C1    = O_C0 + SZ_BUF;
constexpr size_t O_A     = O_C1 + SZ_BUF;
constexpr size_t O_B     = O_A  + SZ_BUF;
constexpr size_t O_O1    = O_B  + SZ_BUF;               // NNZ*32
constexpr size_t O_O2    = O_O1 + (size_t)NNZv * 32;    // NNZ*64
constexpr size_t O_CNTR  = O_O2 + (size_t)NNZv * 64;
constexpr size_t O_GSQ   = O_CNTR + N_ENT;              // 1024*64
constexpr size_t O_GSUM  = O_GSQ + GSQ_SLOTS * 64;
constexpr size_t O_S     = O_GSUM + 64;
constexpr size_t O_T     = O_S + 64;
constexpr size_t O_CONST = O_T + 64;
constexpr size_t O_WEFF  = O_CONST + 64;                // 2*64*64
constexpr size_t O_G     = O_WEFF + 8192;               // 32*16
constexpr size_t O_CV    = O_G + 512;
constexpr size_t SCRATCH_TOTAL = O_CV + 64;

__device__ __align__(16) float g_scratch[SCRATCH_TOTAL];

// ------------- packed f32x2 + vector-red helpers ----------------------------
DEVFN void fma2(u64& d, u64 a, u64 b) {
    asm("fma.rn.f32x2 %0, %1, %2, %0;" : "+l"(d) : "l"(a), "l"(b));
}
DEVFN u64 pack2(float x, float y) {
    u64 u; asm("mov.b64 %0, {%1, %2};" : "=l"(u) : "f"(x), "f"(y)); return u;
}
DEVFN u64 splat2(float x) { return pack2(x, x); }
DEVFN float2 unpack2(u64 u) {
    float2 v; asm("mov.b64 {%0, %1}, %2;" : "=f"(v.x), "=f"(v.y) : "l"(u)); return v;
}
DEVFN void redv4(float* p, float4 v) {
    asm volatile("red.global.add.v4.f32 [%0], {%1, %2, %3, %4};"
                 :: "l"(p), "f"(v.x), "f"(v.y), "f"(v.z), "f"(v.w) : "memory");
}
DEVFN void red1(float* p, float v) {
    asm volatile("red.global.add.f32 [%0], %1;" :: "l"(p), "f"(v) : "memory");
}
DEVFN float lane4(float4 v, int s) {
    return (s == 0) ? v.x : (s == 1) ? v.y : (s == 2) ? v.z : v.w;
}

template<int NC>
DEVFN void accum_pair(u64* acc, const float* WxRow, const float* WyRow, float x, float y) {
    u64 x2 = splat2(x), y2 = splat2(y);
    const u64* w0 = reinterpret_cast<const u64*>(WxRow);
    const u64* w1 = reinterpret_cast<const u64*>(WyRow);
#pragma unroll
    for (int c = 0; c < NC / 2; ++c) fma2(acc[c], x2, w0[c]);
#pragma unroll
    for (int c = 0; c < NC / 2; ++c) fma2(acc[c], y2, w1[c]);
}
template<int NC>
DEVFN void accum_one(u64* acc, const float* WRow, float x) {
    u64 x2 = splat2(x);
    const u64* w0 = reinterpret_cast<const u64*>(WRow);
#pragma unroll
    for (int c = 0; c < NC / 2; ++c) fma2(acc[c], x2, w0[c]);
}

// ------------- zeroing kernel (no memset nodes) -----------------------------
__global__ void k_zero(float4* p, int n4) {
    int i = blockIdx.x * 256 + threadIdx.x;
    int step = gridDim.x * 256;
    for (; i < n4; i += step) p[i] = make_float4(0.f, 0.f, 0.f, 0.f);
}

// ------------- pass 0 (paired): counts + segment sums of raw input ----------
__global__ void __launch_bounds__(256)
k_sum_input(const float* __restrict__ vals, const int* __restrict__ row,
            const int* __restrict__ col, const int* __restrict__ perm,
            float* rsum, float* csum, float* cntR) {
    int j = blockIdx.x * 256 + threadIdx.x;
    if (j >= HALFv) return;
    int j2 = perm[j];
    int r = row[j], c = col[j];
    red1(cntR + r, 1.0f);
    red1(cntR + c, 1.0f);
    const float4* v4  = reinterpret_cast<const float4*>(vals + (size_t)j  * 16);
    const float4* w4  = reinterpret_cast<const float4*>(vals + (size_t)j2 * 16);
#pragma unroll
    for (int q = 0; q < 4; ++q) {
        float4 v = v4[q];
        redv4(rsum + (size_t)r * 16 + 4 * q, v);
        redv4(csum + (size_t)c * 16 + 4 * q, v);
        float4 w = w4[q];
        redv4(rsum + (size_t)c * 16 + 4 * q, w);
        redv4(csum + (size_t)r * 16 + 4 * q, w);
    }
}

// ------------- gsum[c] = sum_i rowsum[i][c] ---------------------------------
template<int COUT>
__global__ void __launch_bounds__(256)
k_reduce(const float* __restrict__ rs, float* gsum) {
    constexpr int Q = COUT / 4;
    int tg = blockIdx.x * 256 + threadIdx.x;
    int q = tg % Q, i0 = tg / Q;
    int step = (gridDim.x * 256) / Q;
    float4 p = make_float4(0.f, 0.f, 0.f, 0.f);
    const float4* rs4 = reinterpret_cast<const float4*>(rs);
    for (int i = i0; i < N_ENT; i += step) {
        float4 x = rs4[(size_t)i * Q + q];
        p.x += x.x; p.y += x.y; p.z += x.z; p.w += x.w;
    }
    redv4(gsum + 4 * q, p);
}

// ------------- per-channel norm stats ---------------------------------------
template<int CN>
__global__ void k_stats(const float* __restrict__ gsum, const float* __restrict__ gsq,
                        float* s, float* t) {
    int c = threadIdx.x;
    if (c >= CN) return;
    float sq = 0.f;
    for (int k = 0; k < GSQ_SLOTS; ++k) sq += gsq[(size_t)k * CN + c];
    float m   = gsum[c] * INV_NNZ;
    float var = sq * INV_NNZ - m * m;
    float sc  = rsqrtf(var + EPSv);
    s[c] = sc;
    t[c] = -m * sc;
}
__global__ void k_stats_ident(float* s, float* t) {
    s[threadIdx.x] = 1.0f; t[threadIdx.x] = 0.0f;
}

// ------------- fold norm into next layer weights ----------------------------
template<int CIN, int COUT>
__global__ void k_prep(const float* __restrict__ W, const float* __restrict__ b,
                       const float* __restrict__ gsum, const float* __restrict__ s,
                       const float* __restrict__ t, float* Weff, float* constv) {
    int tid = threadIdx.x;
    for (int i = tid; i < 2 * CIN * COUT; i += blockDim.x) {
        int k = (i % (CIN * COUT)) / COUT;
        Weff[i] = s[k] * W[i];
    }
    if (tid < COUT) {
        float acc = b[tid];
        for (int k = 0; k < CIN; ++k) {
            float tk  = t[k];
            float tmt = fmaf(gsum[k] * INV_NNZ, s[k], tk);  // global-mean feature
            acc += tk * (W[k * COUT + tid] + W[CIN * COUT + k * COUT + tid])
                 + tmt * W[6 * CIN * COUT + k * COUT + tid];
        }
        constv[tid] = acc;
    }
}

// ------------- per-entity A/B precompute (ops 2..5) -------------------------
template<int CIN, int COUT>
__global__ void __launch_bounds__(256)
k_entity(const float* __restrict__ rs, const float* __restrict__ cs,
         const float* __restrict__ cntR,
         const float* __restrict__ sv, const float* __restrict__ tv,
         const float* __restrict__ W, float* __restrict__ Ab, float* __restrict__ Bb) {
    __shared__ __align__(16) float sW[4 * CIN * COUT];
    __shared__ float ss[CIN], st[CIN];
    int tid = threadIdx.x;
    for (int i = tid; i < 4 * CIN * COUT; i += 256) sW[i] = W[2 * CIN * COUT + i];
    if (tid < CIN) { ss[tid] = sv[tid]; st[tid] = tv[tid]; }
    __syncthreads();

    int gid = blockIdx.x * 256 + tid;
    int i = gid >> 1, half = gid & 1;
    if (i >= N_ENT) return;

    float cr = cntR[i];
    float ir = cr > 0.f ? 1.f / cr : 0.f;

    u64 acc[COUT / 2];
#pragma unroll
    for (int q = 0; q < COUT / 2; ++q) acc[q] = 0ull;

    const float* Wa = sW + (size_t)half * CIN * COUT;        // W2 / W3
    const float* Wb = sW + (size_t)(2 + half) * CIN * COUT;  // W4 / W5

    const float4* r4 = reinterpret_cast<const float4*>(rs + (size_t)i * CIN);
    const float4* c4 = reinterpret_cast<const float4*>(cs + (size_t)i * CIN);
    for (int k4 = 0; k4 < CIN / 4; ++k4) {
        float4 rv = r4[k4], cv = c4[k4];
#pragma unroll
        for (int s4 = 0; s4 < 4; ++s4) {
            int k = 4 * k4 + s4;
            float fr = (cr > 0.f) ? fmaf(lane4(rv, s4) * ir, ss[k], st[k]) : 0.f;
            float fc = (cr > 0.f) ? fmaf(lane4(cv, s4) * ir, ss[k], st[k]) : 0.f;
            accum_pair<COUT>(acc, Wa + k * COUT, Wb + k * COUT, fr, fc);
        }
    }
    float* dst = (half ? Bb : Ab) + (size_t)i * COUT;
    float4* d4 = reinterpret_cast<float4*>(dst);
#pragma unroll
    for (int q = 0; q < COUT / 4; ++q) {
        float2 lo = unpack2(acc[2 * q]), hi = unpack2(acc[2 * q + 1]);
        d4[q] = make_float4(lo.x, lo.y, hi.x, hi.y);
    }
}

// ------------- main paired per-nnz kernel, channel-split ---------------------
// Pair (j, perm[j]) handled by TPP = COUT/16 threads; each owns 16 channels.
// acc0[8]+acc1[8]+sq[8] u64 = 48 regs of accumulator state -> no spills.
template<int CIN, int COUT, int ITER, bool STORE_O, bool DO_COL>
__global__ void __launch_bounds__(256)
k_mainp(const float* __restrict__ vin, const int* __restrict__ row,
        const int* __restrict__ col, const int* __restrict__ perm,
        const float* __restrict__ Weff, const float* __restrict__ constv,
        const float* __restrict__ Ab, const float* __restrict__ Bb,
        float* __restrict__ o, float* __restrict__ rsum,
        float* __restrict__ csum, float* __restrict__ gsq) {
    constexpr int CHUNK = 16;
    constexpr int TPP   = COUT / CHUNK;       // 2 or 4
    constexpr int PPB   = 256 / TPP;          // pairs per block per iter

    __shared__ __align__(16) float sW[2 * CIN * COUT];
    __shared__ float sC[COUT];
    int tid = threadIdx.x;
    for (int i = tid; i < 2 * CIN * COUT; i += 256) sW[i] = Weff[i];
    if (tid < COUT) sC[tid] = constv[tid];
    __syncthreads();

    int ch    = tid % TPP;
    int slotp = tid / TPP;
    int cbase = ch * CHUNK;

    u64 sq[CHUNK / 2];
#pragma unroll
    for (int q = 0; q < CHUNK / 2; ++q) sq[q] = 0ull;

    for (int it = 0; it < ITER; ++it) {
        int j = (blockIdx.x * ITER + it) * PPB + slotp;
        if (j >= HALFv) break;
        int j2 = perm[j];
        int r = row[j], c = col[j];

        u64 acc0[CHUNK / 2], acc1[CHUNK / 2];
        const float4* Ar = reinterpret_cast<const float4*>(Ab + (size_t)r * COUT + cbase);
        const float4* Bc = reinterpret_cast<const float4*>(Bb + (size_t)c * COUT + cbase);
        const float4* Ac = reinterpret_cast<const float4*>(Ab + (size_t)c * COUT + cbase);
        const float4* Br = reinterpret_cast<const float4*>(Bb + (size_t)r * COUT + cbase);
#pragma unroll
        for (int q = 0; q < CHUNK / 4; ++q) {
            float4 a = __ldg(Ar + q), b = __ldg(Bc + q);
            acc0[2 * q]     = pack2(a.x + b.x + sC[cbase + 4 * q],
                                    a.y + b.y + sC[cbase + 4 * q + 1]);
            acc0[2 * q + 1] = pack2(a.z + b.z + sC[cbase + 4 * q + 2],
                                    a.w + b.w + sC[cbase + 4 * q + 3]);
            float4 a2 = __ldg(Ac + q), b2 = __ldg(Br + q);
            acc1[2 * q]     = pack2(a2.x + b2.x + sC[cbase + 4 * q],
                                    a2.y + b2.y + sC[cbase + 4 * q + 1]);
            acc1[2 * q + 1] = pack2(a2.z + b2.z + sC[cbase + 4 * q + 2],
                                    a2.w + b2.w + sC[cbase + 4 * q + 3]);
        }

        const float4* v4 = reinterpret_cast<const float4*>(vin + (size_t)j  * CIN);
        const float4* g4 = reinterpret_cast<const float4*>(vin + (size_t)j2 * CIN);
#pragma unroll
        for (int k4 = 0; k4 < CIN / 4; ++k4) {
            float4 xv = __ldg(v4 + k4);
            float4 yv = __ldg(g4 + k4);
#pragma unroll
            for (int s4 = 0; s4 < 4; ++s4) {
                int k = 4 * k4 + s4;
                float x = lane4(xv, s4), y = lane4(yv, s4);
                const float* W0 = sW + k * COUT + cbase;
                const float* W1 = sW + CIN * COUT + k * COUT + cbase;
                accum_pair<CHUNK>(acc0, W0, W1, x, y);   // h[j]  chunk
                accum_pair<CHUNK>(acc1, W0, W1, y, x);   // h[j2] chunk
            }
        }

        float4* o4a = STORE_O ? reinterpret_cast<float4*>(o + (size_t)j  * COUT + cbase) : nullptr;
        float4* o4b = STORE_O ? reinterpret_cast<float4*>(o + (size_t)j2 * COUT + cbase) : nullptr;
#pragma unroll
        for (int q = 0; q < CHUNK / 4; ++q) {
            float2 lo0 = unpack2(acc0[2 * q]), hi0 = unpack2(acc0[2 * q + 1]);
            float4 h0 = make_float4(fmaxf(lo0.x, 0.f), fmaxf(lo0.y, 0.f),
                                    fmaxf(hi0.x, 0.f), fmaxf(hi0.y, 0.f));
            float2 lo1 = unpack2(acc1[2 * q]), hi1 = unpack2(acc1[2 * q + 1]);
            float4 h1 = make_float4(fmaxf(lo1.x, 0.f), fmaxf(lo1.y, 0.f),
                                    fmaxf(hi1.x, 0.f), fmaxf(hi1.y, 0.f));
            if (STORE_O) { o4a[q] = h0; o4b[q] = h1; }
            redv4(rsum + (size_t)r * COUT + cbase + 4 * q, h0);
            redv4(rsum + (size_t)c * COUT + cbase + 4 * q, h1);
            if (DO_COL) {
                redv4(csum + (size_t)c * COUT + cbase + 4 * q, h0);
                redv4(csum + (size_t)r * COUT + cbase + 4 * q, h1);
            }
            u64 p0 = pack2(h0.x, h0.y), p1 = pack2(h0.z, h0.w);
            u64 p2 = pack2(h1.x, h1.y), p3 = pack2(h1.z, h1.w);
            fma2(sq[2 * q],     p0, p0); fma2(sq[2 * q + 1], p1, p1);
            fma2(sq[2 * q],     p2, p2); fma2(sq[2 * q + 1], p3, p3);
        }
    }

    int slot = (blockIdx.x * 256 + tid) & (GSQ_SLOTS - 1);
    float* gq = gsq + (size_t)slot * COUT + cbase;
#pragma unroll
    for (int q = 0; q < CHUNK / 4; ++q) {
        float2 lo = unpack2(sq[2 * q]), hi = unpack2(sq[2 * q + 1]);
        redv4(gq + 4 * q, make_float4(lo.x, lo.y, hi.x, hi.y));
    }
}

// ------------- head: G = Wp@Wl, cvec = bp@Wl + bl ---------------------------
__global__ void k_head_prep(const float* __restrict__ Wp, const float* __restrict__ bp,
                            const float* __restrict__ Wl, const float* __restrict__ bl,
                            float* G, float* cvec) {
    int tid = threadIdx.x;
    if (tid < 32 * 16) {
        int kin = tid >> 4, c = tid & 15;
        float g = 0.f;
        for (int e = 0; e < 16; ++e) g += Wp[kin * 16 + e] * Wl[e * 16 + c];
        G[tid] = g;
    }
    if (tid < 16) {
        float cv = bl[tid];
        for (int e = 0; e < 16; ++e) cv += bp[e] * Wl[e * 16 + tid];
        cvec[tid] = cv;
    }
}

__global__ void __launch_bounds__(256)
k_final(const float* __restrict__ rs, const float* __restrict__ cntR,
        const float* __restrict__ sv, const float* __restrict__ tv,
        const float* __restrict__ G, const float* __restrict__ cvec,
        float* __restrict__ out) {
    __shared__ __align__(16) float sG[32 * 16];
    __shared__ float scv[16], ss[32], st[32];
    int tid = threadIdx.x;
    for (int i = tid; i < 512; i += 256) sG[i] = G[i];
    if (tid < 16) scv[tid] = cvec[tid];
    if (tid < 32) { ss[tid] = sv[tid]; st[tid] = tv[tid]; }
    __syncthreads();

    int i = blockIdx.x * 256 + tid;
    if (i >= N_ENT) return;
    float cr = cntR[i];
    float ir = cr > 0.f ? 1.f / cr : 0.f;

    u64 acc[8];
#pragma unroll
    for (int q = 0; q < 8; ++q) acc[q] = pack2(scv[2 * q], scv[2 * q + 1]);

    const float4* r4 = reinterpret_cast<const float4*>(rs + (size_t)i * 32);
    for (int k4 = 0; k4 < 8; ++k4) {
        float4 rv = r4[k4];
#pragma unroll
        for (int s4 = 0; s4 < 4; ++s4) {
            int k = 4 * k4 + s4;
            float f = (cr > 0.f) ? fmaf(lane4(rv, s4) * ir, ss[k], st[k]) : 0.f;
            accum_one<16>(acc, sG + k * 16, f);
        }
    }
    float4* d4 = reinterpret_cast<float4*>(out + (size_t)i * 16);
#pragma unroll
    for (int q = 0; q < 4; ++q) {
        float2 lo = unpack2(acc[2 * q]), hi = unpack2(acc[2 * q + 1]);
        d4[q] = make_float4(lo.x, lo.y, hi.x, hi.y);
    }
}

// ------------- host orchestration -------------------------------------------
extern "C" void kernel_launch(void* const* d_in, const int* in_sizes, int n_in,
                              void* d_out, int out_size) {
    const float* values = (const float*)d_in[0];
    const int*   row    = (const int*)d_in[1];
    const int*   col    = (const int*)d_in[2];
    const int*   perm   = (const int*)d_in[3];
    const float* W1 = (const float*)d_in[4];  const float* b1 = (const float*)d_in[5];
    const float* W2 = (const float*)d_in[6];  const float* b2 = (const float*)d_in[7];
    const float* W3 = (const float*)d_in[8];  const float* b3 = (const float*)d_in[9];
    const float* Wp = (const float*)d_in[10]; const float* bp = (const float*)d_in[11];
    const float* Wl = (const float*)d_in[12]; const float* bl = (const float*)d_in[13];
    float* out = (float*)d_out;

    float* S = nullptr;
    cudaGetSymbolAddress((void**)&S, g_scratch);

    float *R0 = S + O_R0, *R1 = S + O_R1, *C0 = S + O_C0, *C1 = S + O_C1;
    float *A  = S + O_A,  *B  = S + O_B;
    float *o1 = S + O_O1, *o2 = S + O_O2;
    float *cntR = S + O_CNTR;
    float *gsq = S + O_GSQ, *gsum = S + O_GSUM;
    float *sb = S + O_S, *tb = S + O_T, *cvv = S + O_CONST, *Weff = S + O_WEFF;
    float *G = S + O_G, *cvec = S + O_CV;

    auto zero = [](float* p, size_t n) {
        int n4 = (int)(n / 4);
        int grid = (n4 + 255) / 256; if (grid > 2048) grid = 2048;
        k_zero<<<grid, 256>>>((float4*)p, n4);
    };
    constexpr int GS   = (HALFv + 255) / 256;
    // pairs-per-block: TPP=2 -> 128, TPP=4 -> 64 ; ITER=4
    constexpr int GP2  = (HALFv + 128 * 4 - 1) / (128 * 4);   // COUT=32 layers
    constexpr int GP4  = (HALFv + 64 * 4 - 1)  / (64 * 4);    // COUT=64 layer
    constexpr int GE   = (2 * N_ENT + 255) / 256;

    // ---- layer 1 (16 -> 32), s=1, t=0 ----
    zero(R0, 4 * SZ_BUF);                    // R0,R1,C0,C1
    zero(cntR, N_ENT);
    zero(gsq, GSQ_SLOTS * 64 + 64);          // gsq + gsum
    k_sum_input<<<GS, 256>>>(values, row, col, perm, R0, C0, cntR);
    k_reduce<16><<<64, 256>>>(R0, gsum);
    k_stats_ident<<<1, 64>>>(sb, tb);
    k_prep<16, 32><<<1, 256>>>(W1, b1, gsum, sb, tb, Weff, cvv);
    k_entity<16, 32><<<GE, 256>>>(R0, C0, cntR, sb, tb, W1, A, B);
    k_mainp<16, 32, 4, true, true><<<GP2, 256>>>(values, row, col, perm, Weff, cvv,
                                                 A, B, o1, R1, C1, gsq);
    // ---- layer 2 (32 -> 64) ----
    zero(gsum, 64);
    k_reduce<32><<<64, 256>>>(R1, gsum);
    k_stats<32><<<1, 64>>>(gsum, gsq, sb, tb);
    k_prep<32, 64><<<1, 256>>>(W2, b2, gsum, sb, tb, Weff, cvv);
    k_entity<32, 64><<<GE, 256>>>(R1, C1, cntR, sb, tb, W2, A, B);
    zero(R0, SZ_BUF); zero(C0, SZ_BUF); zero(gsq, GSQ_SLOTS * 64);
    k_mainp<32, 64, 4, true, true><<<GP4, 256>>>(o1, row, col, perm, Weff, cvv,
                                                 A, B, o2, R0, C0, gsq);
    // ---- layer 3 (64 -> 32), output not materialized ----
    zero(gsum, 64);
    k_reduce<64><<<64, 256>>>(R0, gsum);
    k_stats<64><<<1, 64>>>(gsum, gsq, sb, tb);
    k_prep<64, 32><<<1, 256>>>(W3, b3, gsum, sb, tb, Weff, cvv);
    k_entity<64, 32><<<GE, 256>>>(R0, C0, cntR, sb, tb, W3, A, B);
    zero(R1, SZ_BUF); zero(gsq, GSQ_SLOTS * 64);
    k_mainp<64, 32, 4, false, false><<<GP2, 256>>>(o2, row, col, perm, Weff, cvv,
                                                   A, B, nullptr, R1, nullptr, gsq);
    // ---- head ----
    zero(gsum, 64);
    k_reduce<32><<<64, 256>>>(R1, gsum);
    k_stats<32><<<1, 64>>>(gsum, gsq, sb, tb);
    k_head_prep<<<1, 512>>>(Wp, bp, Wl, bl, G, cvec);
    k_final<<<(N_ENT + 255) / 256, 256>>>(R1, cntR, sb, tb, G, cvec, out);
}

// round 5
// speedup vs baseline: 1.2995x; 1.0850x over previous
#include <cuda_runtime.h>

using u64 = unsigned long long;
#define DEVFN __device__ __forceinline__

constexpr int    N_ENT   = 100000;
constexpr int    NNZv    = 1600000;
constexpr int    HALFv   = NNZv / 2;
constexpr float  EPSv    = 1e-5f;
constexpr float  INV_NNZ = 1.0f / 1600000.0f;
constexpr int    SLOTS   = 256;     // slot tables for gsum/gsq partial reds

// ------------- scratch arena (static __device__, no runtime allocs) ---------
// [zeroed region first: one upfront k_zero covers O_R0 .. ZERO_TOTAL)
constexpr size_t O_R0   = 0;                                // N*16
constexpr size_t O_C0   = O_R0 + (size_t)N_ENT * 16;        // N*16
constexpr size_t O_R1   = O_C0 + (size_t)N_ENT * 16;        // N*32
constexpr size_t O_C1   = O_R1 + (size_t)N_ENT * 32;        // N*32
constexpr size_t O_R2   = O_C1 + (size_t)N_ENT * 32;        // N*64
constexpr size_t O_C2   = O_R2 + (size_t)N_ENT * 64;        // N*64
constexpr size_t O_R3   = O_C2 + (size_t)N_ENT * 64;        // N*32
constexpr size_t O_CNT  = O_R3 + (size_t)N_ENT * 32;        // N
constexpr size_t O_GS0  = O_CNT + N_ENT;                    // SLOTS*16
constexpr size_t O_GS1  = O_GS0 + SLOTS * 16;               // SLOTS*32
constexpr size_t O_GS2  = O_GS1 + SLOTS * 32;               // SLOTS*64
constexpr size_t O_GS3  = O_GS2 + SLOTS * 64;               // SLOTS*32
constexpr size_t O_Q1   = O_GS3 + SLOTS * 32;               // SLOTS*32
constexpr size_t O_Q2   = O_Q1 + SLOTS * 32;                // SLOTS*64
constexpr size_t O_Q3   = O_Q2 + SLOTS * 64;                // SLOTS*32
constexpr size_t ZERO_TOTAL = O_Q3 + SLOTS * 32;
// [not zeroed]
constexpr size_t O_A    = ZERO_TOTAL;                       // N*64
constexpr size_t O_B    = O_A + (size_t)N_ENT * 64;         // N*64
constexpr size_t O_O1   = O_B + (size_t)N_ENT * 64;         // NNZ*32
constexpr size_t O_O2   = O_O1 + (size_t)NNZv * 32;         // NNZ*64
constexpr size_t O_SB   = O_O2 + (size_t)NNZv * 64;         // 64
constexpr size_t O_TB   = O_SB + 64;
constexpr size_t O_CONST= O_TB + 64;
constexpr size_t O_WEFF = O_CONST + 64;                     // 2*64*64
constexpr size_t O_G    = O_WEFF + 8192;                    // 512
constexpr size_t O_CV   = O_G + 512;
constexpr size_t SCRATCH_TOTAL = O_CV + 64;

__device__ __align__(16) float g_scratch[SCRATCH_TOTAL];

// ------------- packed f32x2 / red / shuffle helpers -------------------------
DEVFN void fma2(u64& d, u64 a, u64 b) {
    asm("fma.rn.f32x2 %0, %1, %2, %0;" : "+l"(d) : "l"(a), "l"(b));
}
DEVFN void add2(u64& d, u64 o) {
    asm("add.rn.f32x2 %0, %0, %1;" : "+l"(d) : "l"(o));
}
DEVFN u64 pack2(float x, float y) {
    u64 u; asm("mov.b64 %0, {%1, %2};" : "=l"(u) : "f"(x), "f"(y)); return u;
}
DEVFN u64 splat2(float x) { return pack2(x, x); }
DEVFN float2 unpack2(u64 u) {
    float2 v; asm("mov.b64 {%0, %1}, %2;" : "=f"(v.x), "=f"(v.y) : "l"(u)); return v;
}
DEVFN void redv4(float* p, float4 v) {
    asm volatile("red.global.add.v4.f32 [%0], {%1, %2, %3, %4};"
                 :: "l"(p), "f"(v.x), "f"(v.y), "f"(v.z), "f"(v.w) : "memory");
}
DEVFN void red1(float* p, float v) {
    asm volatile("red.global.add.f32 [%0], %1;" :: "l"(p), "f"(v) : "memory");
}
DEVFN float lane4(float4 v, int s) {
    return (s == 0) ? v.x : (s == 1) ? v.y : (s == 2) ? v.z : v.w;
}
// butterfly sum across lanes whose lane%START differ; all lanes end with class total
template<int START, int NU>
DEVFN void warp_reduce2(u64* v) {
#pragma unroll
    for (int off = START; off < 32; off <<= 1) {
#pragma unroll
        for (int q = 0; q < NU; ++q) {
            u64 o = __shfl_xor_sync(0xFFFFFFFFu, v[q], off);
            add2(v[q], o);
        }
    }
}

template<int NC>
DEVFN void accum_pair(u64* acc, const float* WxRow, const float* WyRow, float x, float y) {
    u64 x2 = splat2(x), y2 = splat2(y);
    const u64* w0 = reinterpret_cast<const u64*>(WxRow);
    const u64* w1 = reinterpret_cast<const u64*>(WyRow);
#pragma unroll
    for (int c = 0; c < NC / 2; ++c) fma2(acc[c], x2, w0[c]);
#pragma unroll
    for (int c = 0; c < NC / 2; ++c) fma2(acc[c], y2, w1[c]);
}
template<int NC>
DEVFN void accum_one(u64* acc, const float* WRow, float x) {
    u64 x2 = splat2(x);
    const u64* w0 = reinterpret_cast<const u64*>(WRow);
#pragma unroll
    for (int c = 0; c < NC / 2; ++c) fma2(acc[c], x2, w0[c]);
}

// ------------- single upfront zero ------------------------------------------
__global__ void k_zero(float4* p, int n4) {
    int i = blockIdx.x * 256 + threadIdx.x;
    int step = gridDim.x * 256;
    for (; i < n4; i += step) p[i] = make_float4(0.f, 0.f, 0.f, 0.f);
}

// ------------- pass 0: counts + input segment sums + global-sum slots -------
__global__ void __launch_bounds__(256)
k_sum_input(const float* __restrict__ vals, const int* __restrict__ row,
            const int* __restrict__ col, float* rsum, float* csum,
            float* cnt, float* gslots) {
    int j = blockIdx.x * 256 + threadIdx.x;          // grid exact: HALF/256
    int r = row[j], c = col[j];
    red1(cnt + r, 1.0f);
    red1(cnt + c, 1.0f);
    const float4* v4 = reinterpret_cast<const float4*>(vals + (size_t)j * 16);
    const float4* w4 = reinterpret_cast<const float4*>(vals + (size_t)(j + HALFv) * 16);
    u64 gs[8];
#pragma unroll
    for (int q = 0; q < 8; ++q) gs[q] = 0ull;
#pragma unroll
    for (int q = 0; q < 4; ++q) {
        float4 v = v4[q];
        redv4(rsum + (size_t)r * 16 + 4 * q, v);
        redv4(csum + (size_t)c * 16 + 4 * q, v);
        float4 w = w4[q];
        redv4(rsum + (size_t)c * 16 + 4 * q, w);
        redv4(csum + (size_t)r * 16 + 4 * q, w);
        add2(gs[2 * q],     pack2(v.x + w.x, v.y + w.y));
        add2(gs[2 * q + 1], pack2(v.z + w.z, v.w + w.w));
    }
    warp_reduce2<1, 8>(gs);
    if ((threadIdx.x & 31) == 0) {
        int slot = ((blockIdx.x * 256 + threadIdx.x) >> 5) & (SLOTS - 1);
        float* gq = gslots + (size_t)slot * 16;
#pragma unroll
        for (int q = 0; q < 4; ++q) {
            float2 lo = unpack2(gs[2 * q]), hi = unpack2(gs[2 * q + 1]);
            redv4(gq + 4 * q, make_float4(lo.x, lo.y, hi.x, hi.y));
        }
    }
}

// ------------- layer-1 prep (identity norm), runs as extra block of entity1 -
DEVFN void prep_ident_block(const float* __restrict__ W, const float* __restrict__ b,
                            const float* __restrict__ gslots,
                            float* Weff, float* constv) {
    __shared__ float sg[16];
    int tid = threadIdx.x;
    if (tid < 16) {
        float s = 0.f;
        for (int k = 0; k < SLOTS; ++k) s += gslots[(size_t)k * 16 + tid];
        sg[tid] = s * INV_NNZ;
    }
    __syncthreads();
    for (int i = tid; i < 2 * 16 * 32; i += 256) Weff[i] = W[i];
    if (tid < 32) {
        float acc = b[tid];
        for (int k = 0; k < 16; ++k) acc += sg[k] * W[6 * 16 * 32 + k * 32 + tid];
        constv[tid] = acc;
    }
}

// ------------- stats + weight fold for layers 2,3 ---------------------------
template<int CIN, int COUT>
__global__ void __launch_bounds__(256)
k_prep(const float* __restrict__ W, const float* __restrict__ b,
       const float* __restrict__ gslots, const float* __restrict__ qslots,
       float* sb, float* tb, float* Weff, float* constv) {
    __shared__ float ssm[CIN], stm[CIN], sgm[CIN];
    int tid = threadIdx.x;
    if (tid < CIN) {
        float sm = 0.f, sq = 0.f;
        for (int k = 0; k < SLOTS; ++k) {
            sm += gslots[(size_t)k * CIN + tid];
            sq += qslots[(size_t)k * CIN + tid];
        }
        float m   = sm * INV_NNZ;
        float var = sq * INV_NNZ - m * m;
        float sc  = rsqrtf(var + EPSv);
        ssm[tid] = sc; stm[tid] = -m * sc; sgm[tid] = sm;
        sb[tid] = sc; tb[tid] = -m * sc;
    }
    __syncthreads();
    for (int i = tid; i < 2 * CIN * COUT; i += 256) {
        int k = (i % (CIN * COUT)) / COUT;
        Weff[i] = ssm[k] * W[i];
    }
    if (tid < COUT) {
        float acc = b[tid];
        for (int k = 0; k < CIN; ++k) {
            float tk  = stm[k];
            float tmt = fmaf(sgm[k] * INV_NNZ, ssm[k], tk);
            acc += tk * (W[k * COUT + tid] + W[CIN * COUT + k * COUT + tid])
                 + tmt * W[6 * CIN * COUT + k * COUT + tid];
        }
        constv[tid] = acc;
    }
}

// ------------- per-entity A/B precompute (ops 2..5) -------------------------
template<int CIN, int COUT, bool IDENT>
__global__ void __launch_bounds__(256)
k_entity(const float* __restrict__ rs, const float* __restrict__ cs,
         const float* __restrict__ cnt,
         const float* __restrict__ sv, const float* __restrict__ tv,
         const float* __restrict__ W, const float* __restrict__ bvec,
         const float* __restrict__ gslots,
         float* __restrict__ Ab, float* __restrict__ Bb,
         float* Weff, float* constv) {
    if (IDENT && blockIdx.x == gridDim.x - 1) {
        prep_ident_block(W, bvec, gslots, Weff, constv);
        return;
    }
    __shared__ __align__(16) float sW[4 * CIN * COUT];
    __shared__ float ss[CIN], st[CIN];
    int tid = threadIdx.x;
    for (int i = tid; i < 4 * CIN * COUT; i += 256) sW[i] = W[2 * CIN * COUT + i];
    if (!IDENT && tid < CIN) { ss[tid] = sv[tid]; st[tid] = tv[tid]; }
    __syncthreads();

    int gid = blockIdx.x * 256 + tid;
    int i = gid >> 1, half = gid & 1;
    if (i >= N_ENT) return;

    float cr = cnt[i];
    float ir = cr > 0.f ? 1.f / cr : 0.f;

    u64 acc[COUT / 2];
#pragma unroll
    for (int q = 0; q < COUT / 2; ++q) acc[q] = 0ull;

    const float* Wa = sW + (size_t)half * CIN * COUT;        // W2 / W3
    const float* Wb = sW + (size_t)(2 + half) * CIN * COUT;  // W4 / W5

    const float4* r4 = reinterpret_cast<const float4*>(rs + (size_t)i * CIN);
    const float4* c4 = reinterpret_cast<const float4*>(cs + (size_t)i * CIN);
    for (int k4 = 0; k4 < CIN / 4; ++k4) {
        float4 rv = r4[k4], cv = c4[k4];
#pragma unroll
        for (int s4 = 0; s4 < 4; ++s4) {
            int k = 4 * k4 + s4;
            float fr, fc;
            if (IDENT) {
                fr = lane4(rv, s4) * ir;
                fc = lane4(cv, s4) * ir;
            } else {
                fr = (cr > 0.f) ? fmaf(lane4(rv, s4) * ir, ss[k], st[k]) : 0.f;
                fc = (cr > 0.f) ? fmaf(lane4(cv, s4) * ir, ss[k], st[k]) : 0.f;
            }
            accum_pair<COUT>(acc, Wa + k * COUT, Wb + k * COUT, fr, fc);
        }
    }
    float* dst = (half ? Bb : Ab) + (size_t)i * COUT;
    float4* d4 = reinterpret_cast<float4*>(dst);
#pragma unroll
    for (int q = 0; q < COUT / 4; ++q) {
        float2 lo = unpack2(acc[2 * q]), hi = unpack2(acc[2 * q + 1]);
        d4[q] = make_float4(lo.x, lo.y, hi.x, hi.y);
    }
}

// ------------- main paired per-nnz kernel, channel-split ---------------------
// Pair (j, j+HALF) by TPP = COUT/16 threads; register gsum+gsq with warp
// shuffle aggregation. Grids exact -> no divergence, full-mask shuffles.
template<int CIN, int COUT, bool STORE_O, bool DO_COL>
__global__ void __launch_bounds__(256)
k_mainp(const float* __restrict__ vin, const int* __restrict__ row,
        const int* __restrict__ col,
        const float* __restrict__ Weff, const float* __restrict__ constv,
        const float* __restrict__ Ab, const float* __restrict__ Bb,
        float* __restrict__ o, float* __restrict__ rsum,
        float* __restrict__ csum, float* __restrict__ qslots,
        float* __restrict__ gslots) {
    constexpr int CHUNK = 16;
    constexpr int TPP   = COUT / CHUNK;       // 2 or 4
    constexpr int PPB   = 256 / TPP;
    constexpr int ITER  = 5;

    __shared__ __align__(16) float sW[2 * CIN * COUT];
    __shared__ float sC[COUT];
    int tid = threadIdx.x;
    for (int i = tid; i < 2 * CIN * COUT; i += 256) sW[i] = Weff[i];
    if (tid < COUT) sC[tid] = constv[tid];
    __syncthreads();

    int ch    = tid % TPP;
    int slotp = tid / TPP;
    int cbase = ch * CHUNK;

    u64 sq[CHUNK / 2], gs[CHUNK / 2];
#pragma unroll
    for (int q = 0; q < CHUNK / 2; ++q) { sq[q] = 0ull; gs[q] = 0ull; }

#pragma unroll 1
    for (int it = 0; it < ITER; ++it) {
        int j = (blockIdx.x * ITER + it) * PPB + slotp;   // exact, always < HALF
        int r = row[j], c = col[j];

        u64 acc0[CHUNK / 2], acc1[CHUNK / 2];
        const float4* Ar = reinterpret_cast<const float4*>(Ab + (size_t)r * COUT + cbase);
        const float4* Bc = reinterpret_cast<const float4*>(Bb + (size_t)c * COUT + cbase);
        const float4* Ac = reinterpret_cast<const float4*>(Ab + (size_t)c * COUT + cbase);
        const float4* Br = reinterpret_cast<const float4*>(Bb + (size_t)r * COUT + cbase);
#pragma unroll
        for (int q = 0; q < CHUNK / 4; ++q) {
            float4 a = __ldg(Ar + q), b = __ldg(Bc + q);
            acc0[2 * q]     = pack2(a.x + b.x + sC[cbase + 4 * q],
                                    a.y + b.y + sC[cbase + 4 * q + 1]);
            acc0[2 * q + 1] = pack2(a.z + b.z + sC[cbase + 4 * q + 2],
                                    a.w + b.w + sC[cbase + 4 * q + 3]);
            float4 a2 = __ldg(Ac + q), b2 = __ldg(Br + q);
            acc1[2 * q]     = pack2(a2.x + b2.x + sC[cbase + 4 * q],
                                    a2.y + b2.y + sC[cbase + 4 * q + 1]);
            acc1[2 * q + 1] = pack2(a2.z + b2.z + sC[cbase + 4 * q + 2],
                                    a2.w + b2.w + sC[cbase + 4 * q + 3]);
        }

        const float4* v4 = reinterpret_cast<const float4*>(vin + (size_t)j * CIN);
        const float4* g4 = reinterpret_cast<const float4*>(vin + (size_t)(j + HALFv) * CIN);
#pragma unroll
        for (int k4 = 0; k4 < CIN / 4; ++k4) {
            float4 xv = __ldg(v4 + k4);
            float4 yv = __ldg(g4 + k4);
#pragma unroll
            for (int s4 = 0; s4 < 4; ++s4) {
                int k = 4 * k4 + s4;
                float x = lane4(xv, s4), y = lane4(yv, s4);
                const float* W0 = sW + k * COUT + cbase;
                const float* W1 = sW + CIN * COUT + k * COUT + cbase;
                accum_pair<CHUNK>(acc0, W0, W1, x, y);   // h[j]      chunk
                accum_pair<CHUNK>(acc1, W0, W1, y, x);   // h[j+HALF] chunk
            }
        }

        float4* o4a = STORE_O ? reinterpret_cast<float4*>(o + (size_t)j * COUT + cbase) : nullptr;
        float4* o4b = STORE_O ? reinterpret_cast<float4*>(o + (size_t)(j + HALFv) * COUT + cbase) : nullptr;
#pragma unroll
        for (int q = 0; q < CHUNK / 4; ++q) {
            float2 lo0 = unpack2(acc0[2 * q]), hi0 = unpack2(acc0[2 * q + 1]);
            float4 h0 = make_float4(fmaxf(lo0.x, 0.f), fmaxf(lo0.y, 0.f),
                                    fmaxf(hi0.x, 0.f), fmaxf(hi0.y, 0.f));
            float2 lo1 = unpack2(acc1[2 * q]), hi1 = unpack2(acc1[2 * q + 1]);
            float4 h1 = make_float4(fmaxf(lo1.x, 0.f), fmaxf(lo1.y, 0.f),
                                    fmaxf(hi1.x, 0.f), fmaxf(hi1.y, 0.f));
            if (STORE_O) { o4a[q] = h0; o4b[q] = h1; }
            redv4(rsum + (size_t)r * COUT + cbase + 4 * q, h0);
            redv4(rsum + (size_t)c * COUT + cbase + 4 * q, h1);
            if (DO_COL) {
                redv4(csum + (size_t)c * COUT + cbase + 4 * q, h0);
                redv4(csum + (size_t)r * COUT + cbase + 4 * q, h1);
            }
            u64 p0 = pack2(h0.x, h0.y), p1 = pack2(h0.z, h0.w);
            u64 p2 = pack2(h1.x, h1.y), p3 = pack2(h1.z, h1.w);
            fma2(sq[2 * q],     p0, p0); fma2(sq[2 * q + 1], p1, p1);
            fma2(sq[2 * q],     p2, p2); fma2(sq[2 * q + 1], p3, p3);
            add2(gs[2 * q],     p0);     add2(gs[2 * q],     p2);
            add2(gs[2 * q + 1], p1);     add2(gs[2 * q + 1], p3);
        }
    }

    // cross-lane aggregation of gsq/gsum before the (rare) global red
    warp_reduce2<TPP, CHUNK / 2>(sq);
    warp_reduce2<TPP, CHUNK / 2>(gs);
    if ((tid & 31) < TPP) {
        int slot = ((blockIdx.x * 256 + tid) >> 5) & (SLOTS - 1);
        float* q1 = qslots + (size_t)slot * COUT + cbase;
        float* g1 = gslots + (size_t)slot * COUT + cbase;
#pragma unroll
        for (int q = 0; q < CHUNK / 4; ++q) {
            float2 lo = unpack2(sq[2 * q]), hi = unpack2(sq[2 * q + 1]);
            redv4(q1 + 4 * q, make_float4(lo.x, lo.y, hi.x, hi.y));
            float2 lg = unpack2(gs[2 * q]), hg = unpack2(gs[2 * q + 1]);
            redv4(g1 + 4 * q, make_float4(lg.x, lg.y, hg.x, hg.y));
        }
    }
}

// ------------- head: stats + G = Wp@Wl, cvec = bp@Wl + bl -------------------
__global__ void __launch_bounds__(512)
k_prep_head(const float* __restrict__ Wp, const float* __restrict__ bp,
            const float* __restrict__ Wl, const float* __restrict__ bl,
            const float* __restrict__ gslots, const float* __restrict__ qslots,
            float* sb, float* tb, float* G, float* cvec) {
    int tid = threadIdx.x;
    if (tid < 32) {
        float sm = 0.f, sq = 0.f;
        for (int k = 0; k < SLOTS; ++k) {
            sm += gslots[(size_t)k * 32 + tid];
            sq += qslots[(size_t)k * 32 + tid];
        }
        float m   = sm * INV_NNZ;
        float var = sq * INV_NNZ - m * m;
        float sc  = rsqrtf(var + EPSv);
        sb[tid] = sc;
        tb[tid] = -m * sc;
    }
    if (tid < 32 * 16) {
        int kin = tid >> 4, c = tid & 15;
        float g = 0.f;
        for (int e = 0; e < 16; ++e) g += Wp[kin * 16 + e] * Wl[e * 16 + c];
        G[tid] = g;
    }
    if (tid < 16) {
        float cv = bl[tid];
        for (int e = 0; e < 16; ++e) cv += bp[e] * Wl[e * 16 + tid];
        cvec[tid] = cv;
    }
}

__global__ void __launch_bounds__(256)
k_final(const float* __restrict__ rs, const float* __restrict__ cnt,
        const float* __restrict__ sv, const float* __restrict__ tv,
        const float* __restrict__ G, const float* __restrict__ cvec,
        float* __restrict__ out) {
    __shared__ __align__(16) float sG[32 * 16];
    __shared__ float scv[16], ss[32], st[32];
    int tid = threadIdx.x;
    for (int i = tid; i < 512; i += 256) sG[i] = G[i];
    if (tid < 16) scv[tid] = cvec[tid];
    if (tid < 32) { ss[tid] = sv[tid]; st[tid] = tv[tid]; }
    __syncthreads();

    int i = blockIdx.x * 256 + tid;
    if (i >= N_ENT) return;
    float cr = cnt[i];
    float ir = cr > 0.f ? 1.f / cr : 0.f;

    u64 acc[8];
#pragma unroll
    for (int q = 0; q < 8; ++q) acc[q] = pack2(scv[2 * q], scv[2 * q + 1]);

    const float4* r4 = reinterpret_cast<const float4*>(rs + (size_t)i * 32);
    for (int k4 = 0; k4 < 8; ++k4) {
        float4 rv = r4[k4];
#pragma unroll
        for (int s4 = 0; s4 < 4; ++s4) {
            int k = 4 * k4 + s4;
            float f = (cr > 0.f) ? fmaf(lane4(rv, s4) * ir, ss[k], st[k]) : 0.f;
            accum_one<16>(acc, sG + k * 16, f);
        }
    }
    float4* d4 = reinterpret_cast<float4*>(out + (size_t)i * 16);
#pragma unroll
    for (int q = 0; q < 4; ++q) {
        float2 lo = unpack2(acc[2 * q]), hi = unpack2(acc[2 * q + 1]);
        d4[q] = make_float4(lo.x, lo.y, hi.x, hi.y);
    }
}

// ------------- host orchestration -------------------------------------------
extern "C" void kernel_launch(void* const* d_in, const int* in_sizes, int n_in,
                              void* d_out, int out_size) {
    const float* values = (const float*)d_in[0];
    const int*   row    = (const int*)d_in[1];
    const int*   col    = (const int*)d_in[2];
    const float* W1 = (const float*)d_in[4];  const float* b1 = (const float*)d_in[5];
    const float* W2 = (const float*)d_in[6];  const float* b2 = (const float*)d_in[7];
    const float* W3 = (const float*)d_in[8];  const float* b3 = (const float*)d_in[9];
    const float* Wp = (const float*)d_in[10]; const float* bp = (const float*)d_in[11];
    const float* Wl = (const float*)d_in[12]; const float* bl = (const float*)d_in[13];
    float* out = (float*)d_out;

    float* S = nullptr;
    cudaGetSymbolAddress((void**)&S, g_scratch);

    float *R0 = S + O_R0, *C0 = S + O_C0, *R1 = S + O_R1, *C1 = S + O_C1;
    float *R2 = S + O_R2, *C2 = S + O_C2, *R3 = S + O_R3;
    float *cnt = S + O_CNT;
    float *GS0 = S + O_GS0, *GS1 = S + O_GS1, *GS2 = S + O_GS2, *GS3 = S + O_GS3;
    float *Q1 = S + O_Q1, *Q2 = S + O_Q2, *Q3 = S + O_Q3;
    float *A  = S + O_A,  *B  = S + O_B;
    float *o1 = S + O_O1, *o2 = S + O_O2;
    float *sb = S + O_SB, *tb = S + O_TB, *cvv = S + O_CONST, *Weff = S + O_WEFF;
    float *G = S + O_G, *cvec = S + O_CV;

    constexpr int GSI = HALFv / 256;               // 3125, exact
    constexpr int GM2T = HALFv / (128 * 5);        // 1250, exact (TPP=2)
    constexpr int GM4T = HALFv / (64 * 5);         // 2500, exact (TPP=4)
    constexpr int GE  = (2 * N_ENT + 255) / 256;   // 782

    // 1. one zero pass over everything that needs it
    k_zero<<<2048, 256>>>((float4*)S, (int)(ZERO_TOTAL / 4));
    // 2. input pass
    k_sum_input<<<GSI, 256>>>(values, row, col, R0, C0, cnt, GS0);
    // 3. entity1 (+ layer-1 prep in last block)
    k_entity<16, 32, true><<<GE + 1, 256>>>(R0, C0, cnt, nullptr, nullptr,
                                            W1, b1, GS0, A, B, Weff, cvv);
    // 4. main layer 1  <- profiled slot
    k_mainp<16, 32, true, true><<<GM2T, 256>>>(values, row, col, Weff, cvv,
                                               A, B, o1, R1, C1, Q1, GS1);
    // 5-7. layer 2
    k_prep<32, 64><<<1, 256>>>(W2, b2, GS1, Q1, sb, tb, Weff, cvv);
    k_entity<32, 64, false><<<GE, 256>>>(R1, C1, cnt, sb, tb,
                                         W2, b2, nullptr, A, B, Weff, cvv);
    k_mainp<32, 64, true, true><<<GM4T, 256>>>(o1, row, col, Weff, cvv,
                                               A, B, o2, R2, C2, Q2, GS2);
    // 8-10. layer 3 (output not materialized)
    k_prep<64, 32><<<1, 256>>>(W3, b3, GS2, Q2, sb, tb, Weff, cvv);
    k_entity<64, 32, false><<<GE, 256>>>(R2, C2, cnt, sb, tb,
                                         W3, b3, nullptr, A, B, Weff, cvv);
    k_mainp<64, 32, false, false><<<GM2T, 256>>>(o2, row, col, Weff, cvv,
                                                 A, B, nullptr, R3, nullptr, Q3, GS3);
    // 11-12. head
    k_prep_head<<<1, 512>>>(Wp, bp, Wl, bl, GS3, Q3, sb, tb, G, cvec);
    k_final<<<(N_ENT + 255) / 256, 256>>>(R3, cnt, sb, tb, G, cvec, out);
}

// round 6
// speedup vs baseline: 1.3041x; 1.0035x over previous
#include <cuda_runtime.h>

using u64 = unsigned long long;
#define DEVFN __device__ __forceinline__

constexpr int    N_ENT   = 100000;
constexpr int    NNZv    = 1600000;
constexpr int    HALFv   = NNZv / 2;
constexpr float  EPSv    = 1e-5f;
constexpr float  INV_NNZ = 1.0f / 1600000.0f;
constexpr int    SLOTS   = 256;

// ------------- scratch arena ------------------------------------------------
// zeroed region first (single upfront k_zero)
constexpr size_t O_RC0  = 0;                                  // N*32  (rsum|csum in16)
constexpr size_t O_RC1  = O_RC0 + (size_t)N_ENT * 32;         // N*64  (rsum|csum c32)
constexpr size_t O_RC2  = O_RC1 + (size_t)N_ENT * 64;         // N*128 (rsum|csum c64)
constexpr size_t O_R3   = O_RC2 + (size_t)N_ENT * 128;        // N*32  (rsum only)
constexpr size_t O_CNT  = O_R3 + (size_t)N_ENT * 32;          // N
constexpr size_t O_GS0  = O_CNT + N_ENT;                      // SLOTS*16 (layer1 gsum slots)
constexpr size_t O_Q1   = O_GS0 + SLOTS * 16;                 // SLOTS*32
constexpr size_t O_Q2   = O_Q1 + SLOTS * 32;                  // SLOTS*64
constexpr size_t O_Q3   = O_Q2 + SLOTS * 64;                  // SLOTS*32
constexpr size_t O_GV1  = O_Q3 + SLOTS * 32;                  // 32
constexpr size_t O_GV2  = O_GV1 + 32;                         // 64
constexpr size_t O_GV3  = O_GV2 + 64;                         // 32
constexpr size_t ZERO_TOTAL = O_GV3 + 32;
// not zeroed
constexpr size_t O_AB   = ZERO_TOTAL;                         // N*128 (A|B interleaved)
constexpr size_t O_O1   = O_AB + (size_t)N_ENT * 128;         // NNZ*32
constexpr size_t O_O2   = O_O1 + (size_t)NNZv * 32;           // NNZ*64
constexpr size_t O_SB   = O_O2 + (size_t)NNZv * 64;
constexpr size_t O_TB   = O_SB + 64;
constexpr size_t O_CONST= O_TB + 64;
constexpr size_t O_WEFF = O_CONST + 64;                       // 2*64*64
constexpr size_t O_G    = O_WEFF + 8192;
constexpr size_t O_CV   = O_G + 512;
constexpr size_t SCRATCH_TOTAL = O_CV + 64;

__device__ __align__(16) float g_scratch[SCRATCH_TOTAL];

// ------------- helpers ------------------------------------------------------
DEVFN void fma2(u64& d, u64 a, u64 b) {
    asm("fma.rn.f32x2 %0, %1, %2, %0;" : "+l"(d) : "l"(a), "l"(b));
}
DEVFN void add2(u64& d, u64 o) {
    asm("add.rn.f32x2 %0, %0, %1;" : "+l"(d) : "l"(o));
}
DEVFN u64 pack2(float x, float y) {
    u64 u; asm("mov.b64 %0, {%1, %2};" : "=l"(u) : "f"(x), "f"(y)); return u;
}
DEVFN u64 splat2(float x) { return pack2(x, x); }
DEVFN float2 unpack2(u64 u) {
    float2 v; asm("mov.b64 {%0, %1}, %2;" : "=f"(v.x), "=f"(v.y) : "l"(u)); return v;
}
DEVFN void redv4(float* p, float4 v) {
    asm volatile("red.global.add.v4.f32 [%0], {%1, %2, %3, %4};"
                 :: "l"(p), "f"(v.x), "f"(v.y), "f"(v.z), "f"(v.w) : "memory");
}
DEVFN void red1(float* p, float v) {
    asm volatile("red.global.add.f32 [%0], %1;" :: "l"(p), "f"(v) : "memory");
}
DEVFN float lane4(float4 v, int s) {
    return (s == 0) ? v.x : (s == 1) ? v.y : (s == 2) ? v.z : v.w;
}
template<int START, int NU>
DEVFN void warp_reduce2(u64* v) {
#pragma unroll
    for (int off = START; off < 32; off <<= 1) {
#pragma unroll
        for (int q = 0; q < NU; ++q) {
            u64 o = __shfl_xor_sync(0xFFFFFFFFu, v[q], off);
            add2(v[q], o);
        }
    }
}
template<int NC>
DEVFN void accum_pair(u64* acc, const float* WxRow, const float* WyRow, float x, float y) {
    u64 x2 = splat2(x), y2 = splat2(y);
    const u64* w0 = reinterpret_cast<const u64*>(WxRow);
    const u64* w1 = reinterpret_cast<const u64*>(WyRow);
#pragma unroll
    for (int c = 0; c < NC / 2; ++c) fma2(acc[c], x2, w0[c]);
#pragma unroll
    for (int c = 0; c < NC / 2; ++c) fma2(acc[c], y2, w1[c]);
}
template<int NC>
DEVFN void accum_one(u64* acc, const float* WRow, float x) {
    u64 x2 = splat2(x);
    const u64* w0 = reinterpret_cast<const u64*>(WRow);
#pragma unroll
    for (int c = 0; c < NC / 2; ++c) fma2(acc[c], x2, w0[c]);
}

// ------------- upfront zero -------------------------------------------------
__global__ void k_zero(float4* p, int n4) {
    int i = blockIdx.x * 256 + threadIdx.x;
    int step = gridDim.x * 256;
    for (; i < n4; i += step) p[i] = make_float4(0.f, 0.f, 0.f, 0.f);
}

// ------------- pass 0: counts + RC0 segment sums + layer1 gsum slots --------
__global__ void __launch_bounds__(256)
k_sum_input(const float* __restrict__ vals, const int* __restrict__ row,
            const int* __restrict__ col, float* rc, float* cnt, float* gslots) {
    int j = blockIdx.x * 256 + threadIdx.x;          // exact grid
    int r = row[j], c = col[j];
    red1(cnt + r, 1.0f);
    red1(cnt + c, 1.0f);
    const float4* v4 = reinterpret_cast<const float4*>(vals + (size_t)j * 16);
    const float4* w4 = reinterpret_cast<const float4*>(vals + (size_t)(j + HALFv) * 16);
    u64 gs[8];
#pragma unroll
    for (int q = 0; q < 8; ++q) gs[q] = 0ull;
#pragma unroll
    for (int q = 0; q < 4; ++q) {
        float4 v = v4[q];
        float4 w = w4[q];
        // RC[r]: rsum += v, csum += w ; RC[c]: rsum += w, csum += v
        redv4(rc + (size_t)r * 32 + 4 * q,      v);
        redv4(rc + (size_t)r * 32 + 16 + 4 * q, w);
        redv4(rc + (size_t)c * 32 + 4 * q,      w);
        redv4(rc + (size_t)c * 32 + 16 + 4 * q, v);
        add2(gs[2 * q],     pack2(v.x + w.x, v.y + w.y));
        add2(gs[2 * q + 1], pack2(v.z + w.z, v.w + w.w));
    }
    warp_reduce2<1, 8>(gs);
    if ((threadIdx.x & 31) == 0) {
        int slot = ((blockIdx.x * 256 + threadIdx.x) >> 5) & (SLOTS - 1);
        float* gq = gslots + (size_t)slot * 16;
#pragma unroll
        for (int q = 0; q < 4; ++q) {
            float2 lo = unpack2(gs[2 * q]), hi = unpack2(gs[2 * q + 1]);
            redv4(gq + 4 * q, make_float4(lo.x, lo.y, hi.x, hi.y));
        }
    }
}

// ------------- gsum[c] = sum_i rsum[i][c] (rsum part of stride-ST table) ----
template<int C, int ST>
__global__ void __launch_bounds__(256)
k_reduce(const float* __restrict__ t, float* gsum) {
    constexpr int Q = C / 4;
    int tg = blockIdx.x * 256 + threadIdx.x;
    int q = tg % Q, i0 = tg / Q;
    int step = (gridDim.x * 256) / Q;
    float4 p = make_float4(0.f, 0.f, 0.f, 0.f);
    for (int i = i0; i < N_ENT; i += step) {
        const float4* src = reinterpret_cast<const float4*>(t + (size_t)i * ST + 4 * q);
        float4 x = *src;
        p.x += x.x; p.y += x.y; p.z += x.z; p.w += x.w;
    }
    u64 pr[2] = { pack2(p.x, p.y), pack2(p.z, p.w) };
    warp_reduce2<Q, 2>(pr);
    if ((threadIdx.x & 31) < Q && (threadIdx.x & 31) == (q & 31)) {
        float2 lo = unpack2(pr[0]), hi = unpack2(pr[1]);
        redv4(gsum + 4 * q, make_float4(lo.x, lo.y, hi.x, hi.y));
    }
}

// ------------- layer-1 prep (identity norm) block ---------------------------
DEVFN void prep_ident_block(const float* __restrict__ W, const float* __restrict__ b,
                            const float* __restrict__ gslots,
                            float* Weff, float* constv) {
    __shared__ float sg[16];
    int tid = threadIdx.x;
    if (tid < 16) {
        float s = 0.f;
        for (int k = 0; k < SLOTS; ++k) s += gslots[(size_t)k * 16 + tid];
        sg[tid] = s * INV_NNZ;
    }
    __syncthreads();
    for (int i = tid; i < 2 * 16 * 32; i += 256) Weff[i] = W[i];
    if (tid < 32) {
        float acc = b[tid];
        for (int k = 0; k < 16; ++k) acc += sg[k] * W[6 * 16 * 32 + k * 32 + tid];
        constv[tid] = acc;
    }
}

// ------------- stats + weight fold (layers 2,3) -----------------------------
template<int CIN, int COUT>
__global__ void __launch_bounds__(256)
k_prep(const float* __restrict__ W, const float* __restrict__ b,
       const float* __restrict__ gsum, const float* __restrict__ qslots,
       float* sb, float* tb, float* Weff, float* constv) {
    __shared__ float ssm[CIN], stm[CIN], sgm[CIN];
    int tid = threadIdx.x;
    if (tid < CIN) {
        float sq = 0.f;
        for (int k = 0; k < SLOTS; ++k) sq += qslots[(size_t)k * CIN + tid];
        float sm  = gsum[tid];
        float m   = sm * INV_NNZ;
        float var = sq * INV_NNZ - m * m;
        float sc  = rsqrtf(var + EPSv);
        ssm[tid] = sc; stm[tid] = -m * sc; sgm[tid] = sm;
        sb[tid] = sc; tb[tid] = -m * sc;
    }
    __syncthreads();
    for (int i = tid; i < 2 * CIN * COUT; i += 256) {
        int k = (i % (CIN * COUT)) / COUT;
        Weff[i] = ssm[k] * W[i];
    }
    if (tid < COUT) {
        float acc = b[tid];
        for (int k = 0; k < CIN; ++k) {
            float tk  = stm[k];
            float tmt = fmaf(sgm[k] * INV_NNZ, ssm[k], tk);
            acc += tk * (W[k * COUT + tid] + W[CIN * COUT + k * COUT + tid])
                 + tmt * W[6 * CIN * COUT + k * COUT + tid];
        }
        constv[tid] = acc;
    }
}

// ------------- per-entity A/B precompute into interleaved AB table ----------
template<int CIN, int COUT, bool IDENT>
__global__ void __launch_bounds__(256)
k_entity(const float* __restrict__ rc, const float* __restrict__ cnt,
         const float* __restrict__ sv, const float* __restrict__ tv,
         const float* __restrict__ W, const float* __restrict__ bvec,
         const float* __restrict__ gslots,
         float* __restrict__ AB, float* Weff, float* constv) {
    if (IDENT && blockIdx.x == gridDim.x - 1) {
        prep_ident_block(W, bvec, gslots, Weff, constv);
        return;
    }
    __shared__ __align__(16) float sW[4 * CIN * COUT];
    __shared__ float ss[CIN], st[CIN];
    int tid = threadIdx.x;
    for (int i = tid; i < 4 * CIN * COUT; i += 256) sW[i] = W[2 * CIN * COUT + i];
    if (!IDENT && tid < CIN) { ss[tid] = sv[tid]; st[tid] = tv[tid]; }
    __syncthreads();

    int gid = blockIdx.x * 256 + tid;
    int i = gid >> 1, half = gid & 1;
    if (i >= N_ENT) return;

    float cr = cnt[i];
    float ir = cr > 0.f ? 1.f / cr : 0.f;

    u64 acc[COUT / 2];
#pragma unroll
    for (int q = 0; q < COUT / 2; ++q) acc[q] = 0ull;

    const float* Wa = sW + (size_t)half * CIN * COUT;        // W2 / W3
    const float* Wb = sW + (size_t)(2 + half) * CIN * COUT;  // W4 / W5

    const float4* r4 = reinterpret_cast<const float4*>(rc + (size_t)i * 2 * CIN);
    const float4* c4 = reinterpret_cast<const float4*>(rc + (size_t)i * 2 * CIN + CIN);
    for (int k4 = 0; k4 < CIN / 4; ++k4) {
        float4 rv = r4[k4], cv = c4[k4];
#pragma unroll
        for (int s4 = 0; s4 < 4; ++s4) {
            int k = 4 * k4 + s4;
            float fr, fc;
            if (IDENT) {
                fr = lane4(rv, s4) * ir;
                fc = lane4(cv, s4) * ir;
            } else {
                fr = (cr > 0.f) ? fmaf(lane4(rv, s4) * ir, ss[k], st[k]) : 0.f;
                fc = (cr > 0.f) ? fmaf(lane4(cv, s4) * ir, ss[k], st[k]) : 0.f;
            }
            accum_pair<COUT>(acc, Wa + k * COUT, Wb + k * COUT, fr, fc);
        }
    }
    float* dst = AB + (size_t)i * 2 * COUT + (half ? COUT : 0);
    float4* d4 = reinterpret_cast<float4*>(dst);
#pragma unroll
    for (int q = 0; q < COUT / 4; ++q) {
        float2 lo = unpack2(acc[2 * q]), hi = unpack2(acc[2 * q + 1]);
        d4[q] = make_float4(lo.x, lo.y, hi.x, hi.y);
    }
}

// ------------- main paired per-nnz kernel -----------------------------------
template<int CIN, int COUT, bool STORE_O, bool DO_COL>
__global__ void __launch_bounds__(256, 3)
k_mainp(const float* __restrict__ vin, const int* __restrict__ row,
        const int* __restrict__ col,
        const float* __restrict__ Weff, const float* __restrict__ constv,
        const float* __restrict__ AB,
        float* __restrict__ o, float* __restrict__ rc,
        float* __restrict__ qslots) {
    constexpr int CHUNK = 16;
    constexpr int TPP   = COUT / CHUNK;       // 2 or 4
    constexpr int PPB   = 256 / TPP;
    constexpr int ITER  = 5;
    constexpr int RST   = DO_COL ? 2 * COUT : COUT;   // RC row stride

    __shared__ __align__(16) float sW[2 * CIN * COUT];
    __shared__ float sC[COUT];
    int tid = threadIdx.x;
    for (int i = tid; i < 2 * CIN * COUT; i += 256) sW[i] = Weff[i];
    if (tid < COUT) sC[tid] = constv[tid];
    __syncthreads();

    int ch    = tid % TPP;
    int slotp = tid / TPP;
    int cbase = ch * CHUNK;

    u64 sq[CHUNK / 2];
#pragma unroll
    for (int q = 0; q < CHUNK / 2; ++q) sq[q] = 0ull;

#pragma unroll 1
    for (int it = 0; it < ITER; ++it) {
        int j = (blockIdx.x * ITER + it) * PPB + slotp;   // exact
        int r = row[j], c = col[j];

        u64 acc0[CHUNK / 2], acc1[CHUNK / 2];
        const float* abr = AB + (size_t)r * 2 * COUT;
        const float* abc = AB + (size_t)c * 2 * COUT;
        const float4* Ar = reinterpret_cast<const float4*>(abr + cbase);
        const float4* Br = reinterpret_cast<const float4*>(abr + COUT + cbase);
        const float4* Ac = reinterpret_cast<const float4*>(abc + cbase);
        const float4* Bc = reinterpret_cast<const float4*>(abc + COUT + cbase);
#pragma unroll
        for (int q = 0; q < CHUNK / 4; ++q) {
            float4 a = __ldg(Ar + q), b = __ldg(Bc + q);
            acc0[2 * q]     = pack2(a.x + b.x + sC[cbase + 4 * q],
                                    a.y + b.y + sC[cbase + 4 * q + 1]);
            acc0[2 * q + 1] = pack2(a.z + b.z + sC[cbase + 4 * q + 2],
                                    a.w + b.w + sC[cbase + 4 * q + 3]);
            float4 a2 = __ldg(Ac + q), b2 = __ldg(Br + q);
            acc1[2 * q]     = pack2(a2.x + b2.x + sC[cbase + 4 * q],
                                    a2.y + b2.y + sC[cbase + 4 * q + 1]);
            acc1[2 * q + 1] = pack2(a2.z + b2.z + sC[cbase + 4 * q + 2],
                                    a2.w + b2.w + sC[cbase + 4 * q + 3]);
        }

        const float4* v4 = reinterpret_cast<const float4*>(vin + (size_t)j * CIN);
        const float4* g4 = reinterpret_cast<const float4*>(vin + (size_t)(j + HALFv) * CIN);
#pragma unroll
        for (int k4 = 0; k4 < CIN / 4; ++k4) {
            float4 xv = __ldg(v4 + k4);
            float4 yv = __ldg(g4 + k4);
#pragma unroll
            for (int s4 = 0; s4 < 4; ++s4) {
                int k = 4 * k4 + s4;
                float x = lane4(xv, s4), y = lane4(yv, s4);
                const float* W0 = sW + k * COUT + cbase;
                const float* W1 = sW + CIN * COUT + k * COUT + cbase;
                accum_pair<CHUNK>(acc0, W0, W1, x, y);   // h[j]
                accum_pair<CHUNK>(acc1, W0, W1, y, x);   // h[j+HALF]
            }
        }

        float4* o4a = STORE_O ? reinterpret_cast<float4*>(o + (size_t)j * COUT + cbase) : nullptr;
        float4* o4b = STORE_O ? reinterpret_cast<float4*>(o + (size_t)(j + HALFv) * COUT + cbase) : nullptr;
        float* rcr = rc + (size_t)r * RST + cbase;
        float* rcc = rc + (size_t)c * RST + cbase;
#pragma unroll
        for (int q = 0; q < CHUNK / 4; ++q) {
            float2 lo0 = unpack2(acc0[2 * q]), hi0 = unpack2(acc0[2 * q + 1]);
            float4 h0 = make_float4(fmaxf(lo0.x, 0.f), fmaxf(lo0.y, 0.f),
                                    fmaxf(hi0.x, 0.f), fmaxf(hi0.y, 0.f));
            float2 lo1 = unpack2(acc1[2 * q]), hi1 = unpack2(acc1[2 * q + 1]);
            float4 h1 = make_float4(fmaxf(lo1.x, 0.f), fmaxf(lo1.y, 0.f),
                                    fmaxf(hi1.x, 0.f), fmaxf(hi1.y, 0.f));
            if (STORE_O) { o4a[q] = h0; o4b[q] = h1; }
            redv4(rcr + 4 * q, h0);                       // rsum[r] += h0
            redv4(rcc + 4 * q, h1);                       // rsum[c] += h1
            if (DO_COL) {
                redv4(rcr + COUT + 4 * q, h1);            // csum[r] += h1
                redv4(rcc + COUT + 4 * q, h0);            // csum[c] += h0
            }
            u64 p0 = pack2(h0.x, h0.y), p1 = pack2(h0.z, h0.w);
            u64 p2 = pack2(h1.x, h1.y), p3 = pack2(h1.z, h1.w);
            fma2(sq[2 * q],     p0, p0); fma2(sq[2 * q + 1], p1, p1);
            fma2(sq[2 * q],     p2, p2); fma2(sq[2 * q + 1], p3, p3);
        }
    }

    warp_reduce2<TPP, CHUNK / 2>(sq);
    if ((tid & 31) < TPP) {
        int slot = ((blockIdx.x * 256 + tid) >> 5) & (SLOTS - 1);
        float* q1 = qslots + (size_t)slot * COUT + cbase;
#pragma unroll
        for (int q = 0; q < CHUNK / 4; ++q) {
            float2 lo = unpack2(sq[2 * q]), hi = unpack2(sq[2 * q + 1]);
            redv4(q1 + 4 * q, make_float4(lo.x, lo.y, hi.x, hi.y));
        }
    }
}

// ------------- head ---------------------------------------------------------
__global__ void __launch_bounds__(512)
k_prep_head(const float* __restrict__ Wp, const float* __restrict__ bp,
            const float* __restrict__ Wl, const float* __restrict__ bl,
            const float* __restrict__ gsum, const float* __restrict__ qslots,
            float* sb, float* tb, float* G, float* cvec) {
    int tid = threadIdx.x;
    if (tid < 32) {
        float sq = 0.f;
        for (int k = 0; k < SLOTS; ++k) sq += qslots[(size_t)k * 32 + tid];
        float sm  = gsum[tid];
        float m   = sm * INV_NNZ;
        float var = sq * INV_NNZ - m * m;
        float sc  = rsqrtf(var + EPSv);
        sb[tid] = sc;
        tb[tid] = -m * sc;
    }
    if (tid < 32 * 16) {
        int kin = tid >> 4, c = tid & 15;
        float g = 0.f;
        for (int e = 0; e < 16; ++e) g += Wp[kin * 16 + e] * Wl[e * 16 + c];
        G[tid] = g;
    }
    if (tid < 16) {
        float cv = bl[tid];
        for (int e = 0; e < 16; ++e) cv += bp[e] * Wl[e * 16 + tid];
        cvec[tid] = cv;
    }
}

__global__ void __launch_bounds__(256)
k_final(const float* __restrict__ rs, const float* __restrict__ cnt,
        const float* __restrict__ sv, const float* __restrict__ tv,
        const float* __restrict__ G, const float* __restrict__ cvec,
        float* __restrict__ out) {
    __shared__ __align__(16) float sG[32 * 16];
    __shared__ float scv[16], ss[32], st[32];
    int tid = threadIdx.x;
    for (int i = tid; i < 512; i += 256) sG[i] = G[i];
    if (tid < 16) scv[tid] = cvec[tid];
    if (tid < 32) { ss[tid] = sv[tid]; st[tid] = tv[tid]; }
    __syncthreads();

    int i = blockIdx.x * 256 + tid;
    if (i >= N_ENT) return;
    float cr = cnt[i];
    float ir = cr > 0.f ? 1.f / cr : 0.f;

    u64 acc[8];
#pragma unroll
    for (int q = 0; q < 8; ++q) acc[q] = pack2(scv[2 * q], scv[2 * q + 1]);

    const float4* r4 = reinterpret_cast<const float4*>(rs + (size_t)i * 32);
    for (int k4 = 0; k4 < 8; ++k4) {
        float4 rv = r4[k4];
#pragma unroll
        for (int s4 = 0; s4 < 4; ++s4) {
            int k = 4 * k4 + s4;
            float f = (cr > 0.f) ? fmaf(lane4(rv, s4) * ir, ss[k], st[k]) : 0.f;
            accum_one<16>(acc, sG + k * 16, f);
        }
    }
    float4* d4 = reinterpret_cast<float4*>(out + (size_t)i * 16);
#pragma unroll
    for (int q = 0; q < 4; ++q) {
        float2 lo = unpack2(acc[2 * q]), hi = unpack2(acc[2 * q + 1]);
        d4[q] = make_float4(lo.x, lo.y, hi.x, hi.y);
    }
}

// ------------- host orchestration -------------------------------------------
extern "C" void kernel_launch(void* const* d_in, const int* in_sizes, int n_in,
                              void* d_out, int out_size) {
    const float* values = (const float*)d_in[0];
    const int*   row    = (const int*)d_in[1];
    const int*   col    = (const int*)d_in[2];
    const float* W1 = (const float*)d_in[4];  const float* b1 = (const float*)d_in[5];
    const float* W2 = (const float*)d_in[6];  const float* b2 = (const float*)d_in[7];
    const float* W3 = (const float*)d_in[8];  const float* b3 = (const float*)d_in[9];
    const float* Wp = (const float*)d_in[10]; const float* bp = (const float*)d_in[11];
    const float* Wl = (const float*)d_in[12]; const float* bl = (const float*)d_in[13];
    float* out = (float*)d_out;

    float* S = nullptr;
    cudaGetSymbolAddress((void**)&S, g_scratch);

    float *RC0 = S + O_RC0, *RC1 = S + O_RC1, *RC2 = S + O_RC2, *R3 = S + O_R3;
    float *cnt = S + O_CNT, *GS0 = S + O_GS0;
    float *Q1 = S + O_Q1, *Q2 = S + O_Q2, *Q3 = S + O_Q3;
    float *GV1 = S + O_GV1, *GV2 = S + O_GV2, *GV3 = S + O_GV3;
    float *AB = S + O_AB;
    float *o1 = S + O_O1, *o2 = S + O_O2;
    float *sb = S + O_SB, *tb = S + O_TB, *cvv = S + O_CONST, *Weff = S + O_WEFF;
    float *G = S + O_G, *cvec = S + O_CV;

    constexpr int GSI  = HALFv / 256;          // 3125 exact
    constexpr int GM2T = HALFv / (128 * 5);    // 1250 exact (TPP=2)
    constexpr int GM4T = HALFv / (64 * 5);     // 2500 exact (TPP=4)
    constexpr int GE   = (2 * N_ENT + 255) / 256;

    // 1. zero
    k_zero<<<2048, 256>>>((float4*)S, (int)(ZERO_TOTAL / 4));
    // 2. input pass (RC0, cnt, layer-1 gsum slots)
    k_sum_input<<<GSI, 256>>>(values, row, col, RC0, cnt, GS0);
    // 3. entity1 (+layer-1 prep block)
    k_entity<16, 32, true><<<GE + 1, 256>>>(RC0, cnt, nullptr, nullptr,
                                            W1, b1, GS0, AB, Weff, cvv);
    // 4. main layer 1  <- profiled slot (apples-to-apples vs R5)
    k_mainp<16, 32, true, true><<<GM2T, 256>>>(values, row, col, Weff, cvv,
                                               AB, o1, RC1, Q1);
    // layer 2
    k_reduce<32, 64><<<64, 256>>>(RC1, GV1);
    k_prep<32, 64><<<1, 256>>>(W2, b2, GV1, Q1, sb, tb, Weff, cvv);
    k_entity<32, 64, false><<<GE, 256>>>(RC1, cnt, sb, tb, W2, b2, nullptr,
                                         AB, Weff, cvv);
    k_mainp<32, 64, true, true><<<GM4T, 256>>>(o1, row, col, Weff, cvv,
                                               AB, o2, RC2, Q2);
    // layer 3
    k_reduce<64, 128><<<64, 256>>>(RC2, GV2);
    k_prep<64, 32><<<1, 256>>>(W3, b3, GV2, Q2, sb, tb, Weff, cvv);
    k_entity<64, 32, false><<<GE, 256>>>(RC2, cnt, sb, tb, W3, b3, nullptr,
                                         AB, Weff, cvv);
    k_mainp<64, 32, false, false><<<GM2T, 256>>>(o2, row, col, Weff, cvv,
                                                 AB, nullptr, R3, Q3);
    // head
    k_reduce<32, 32><<<64, 256>>>(R3, GV3);
    k_prep_head<<<1, 512>>>(Wp, bp, Wl, bl, GV3, Q3, sb, tb, G, cvec);
    k_final<<<(N_ENT + 255) / 256, 256>>>(R3, cnt, sb, tb, G, cvec, out);
}

// round 7
// speedup vs baseline: 1.7139x; 1.3142x over previous
#include <cuda_runtime.h>

using u64 = unsigned long long;
#define DEVFN __device__ __forceinline__

constexpr int    N_ENT   = 100000;
constexpr int    NNZv    = 1600000;
constexpr int    HALFv   = NNZv / 2;
constexpr float  EPSv    = 1e-5f;
constexpr float  INV_NNZ = 1.0f / 1600000.0f;
constexpr int    SLOTS   = 256;

// ------------- scratch arena ------------------------------------------------
constexpr size_t O_RC0  = 0;                                  // N*32  (rsum|csum in16)
constexpr size_t O_RC1  = O_RC0 + (size_t)N_ENT * 32;         // N*64  (rsum|csum c32)
constexpr size_t O_RC2  = O_RC1 + (size_t)N_ENT * 64;         // N*128 (rsum|csum c64)
constexpr size_t O_R3   = O_RC2 + (size_t)N_ENT * 128;        // N*32  (rsum only)
constexpr size_t O_CNT  = O_R3 + (size_t)N_ENT * 32;          // N
constexpr size_t O_GS0  = O_CNT + N_ENT;                      // SLOTS*16
constexpr size_t O_Q1   = O_GS0 + SLOTS * 16;                 // SLOTS*32
constexpr size_t O_Q2   = O_Q1 + SLOTS * 32;                  // SLOTS*64
constexpr size_t O_Q3   = O_Q2 + SLOTS * 64;                  // SLOTS*32
constexpr size_t O_GV1  = O_Q3 + SLOTS * 32;                  // 32
constexpr size_t O_GV2  = O_GV1 + 32;                         // 64
constexpr size_t O_GV3  = O_GV2 + 64;                         // 32
constexpr size_t ZERO_TOTAL = O_GV3 + 32;
// not zeroed
constexpr size_t O_AB   = ZERO_TOTAL;                         // N*128 (A|B interleaved)
constexpr size_t O_O1   = O_AB + (size_t)N_ENT * 128;         // NNZ*32
constexpr size_t O_O2   = O_O1 + (size_t)NNZv * 32;           // NNZ*64
constexpr size_t O_SB   = O_O2 + (size_t)NNZv * 64;
constexpr size_t O_TB   = O_SB + 64;
constexpr size_t O_CONST= O_TB + 64;
constexpr size_t O_WEFF = O_CONST + 64;                       // 2*64*64
constexpr size_t O_G    = O_WEFF + 8192;
constexpr size_t O_CV   = O_G + 512;
constexpr size_t SCRATCH_TOTAL = O_CV + 64;

__device__ __align__(16) float g_scratch[SCRATCH_TOTAL];

// ------------- helpers ------------------------------------------------------
DEVFN void fma2(u64& d, u64 a, u64 b) {
    asm("fma.rn.f32x2 %0, %1, %2, %0;" : "+l"(d) : "l"(a), "l"(b));
}
DEVFN void add2(u64& d, u64 o) {
    asm("add.rn.f32x2 %0, %0, %1;" : "+l"(d) : "l"(o));
}
DEVFN u64 pack2(float x, float y) {
    u64 u; asm("mov.b64 %0, {%1, %2};" : "=l"(u) : "f"(x), "f"(y)); return u;
}
DEVFN u64 splat2(float x) { return pack2(x, x); }
DEVFN float2 unpack2(u64 u) {
    float2 v; asm("mov.b64 {%0, %1}, %2;" : "=f"(v.x), "=f"(v.y) : "l"(u)); return v;
}
DEVFN void redv4(float* p, float4 v) {
    asm volatile("red.global.add.v4.f32 [%0], {%1, %2, %3, %4};"
                 :: "l"(p), "f"(v.x), "f"(v.y), "f"(v.z), "f"(v.w) : "memory");
}
DEVFN void red1(float* p, float v) {
    asm volatile("red.global.add.f32 [%0], %1;" :: "l"(p), "f"(v) : "memory");
}
DEVFN float lane4(float4 v, int s) {
    return (s == 0) ? v.x : (s == 1) ? v.y : (s == 2) ? v.z : v.w;
}
template<int START, int NU>
DEVFN void warp_reduce2(u64* v) {
#pragma unroll
    for (int off = START; off < 32; off <<= 1) {
#pragma unroll
        for (int q = 0; q < NU; ++q) {
            u64 o = __shfl_xor_sync(0xFFFFFFFFu, v[q], off);
            add2(v[q], o);
        }
    }
}
template<int NC>
DEVFN void accum_pair(u64* acc, const float* WxRow, const float* WyRow, float x, float y) {
    u64 x2 = splat2(x), y2 = splat2(y);
    const u64* w0 = reinterpret_cast<const u64*>(WxRow);
    const u64* w1 = reinterpret_cast<const u64*>(WyRow);
#pragma unroll
    for (int c = 0; c < NC / 2; ++c) fma2(acc[c], x2, w0[c]);
#pragma unroll
    for (int c = 0; c < NC / 2; ++c) fma2(acc[c], y2, w1[c]);
}
template<int NC>
DEVFN void accum_one(u64* acc, const float* WRow, float x) {
    u64 x2 = splat2(x);
    const u64* w0 = reinterpret_cast<const u64*>(WRow);
#pragma unroll
    for (int c = 0; c < NC / 2; ++c) fma2(acc[c], x2, w0[c]);
}

// ------------- upfront zero -------------------------------------------------
__global__ void k_zero(float4* p, int n4) {
    int i = blockIdx.x * 256 + threadIdx.x;
    int step = gridDim.x * 256;
    for (; i < n4; i += step) p[i] = make_float4(0.f, 0.f, 0.f, 0.f);
}

// ------------- pass 0: TPP=4 channel-split input pass -----------------------
__global__ void __launch_bounds__(256)
k_sum_input(const float* __restrict__ vals, const int* __restrict__ row,
            const int* __restrict__ col, float* rc, float* cnt, float* gslots) {
    int tid = threadIdx.x;
    int ch = tid & 3;                     // 4 threads per pair
    int p  = blockIdx.x * 64 + (tid >> 2);   // exact grid: HALF/64
    int r = row[p], c = col[p];
    if (ch == 0) { red1(cnt + r, 1.0f); red1(cnt + c, 1.0f); }

    float4 v = __ldg(reinterpret_cast<const float4*>(vals + (size_t)p * 16) + ch);
    float4 w = __ldg(reinterpret_cast<const float4*>(vals + (size_t)(p + HALFv) * 16) + ch);

    // RC[i] = [rsum(16) | csum(16)], thread owns 4 channels at offset ch*4
    redv4(rc + (size_t)r * 32 + 4 * ch,      v);   // rsum[r] += v
    redv4(rc + (size_t)r * 32 + 16 + 4 * ch, w);   // csum[r] += w
    redv4(rc + (size_t)c * 32 + 4 * ch,      w);   // rsum[c] += w
    redv4(rc + (size_t)c * 32 + 16 + 4 * ch, v);   // csum[c] += v

    u64 gs[2] = { pack2(v.x + w.x, v.y + w.y), pack2(v.z + w.z, v.w + w.w) };
    warp_reduce2<4, 2>(gs);
    if ((tid & 31) < 4) {
        int slot = ((blockIdx.x * 256 + tid) >> 5) & (SLOTS - 1);
        float2 lo = unpack2(gs[0]), hi = unpack2(gs[1]);
        redv4(gslots + (size_t)slot * 16 + 4 * ch,
              make_float4(lo.x, lo.y, hi.x, hi.y));
    }
}

// ------------- gsum[c] = sum_i rsum[i][c] ------------------------------------
template<int C, int ST>
__global__ void __launch_bounds__(256)
k_reduce(const float* __restrict__ t, float* gsum) {
    constexpr int Q = C / 4;
    int tg = blockIdx.x * 256 + threadIdx.x;
    int q = tg % Q, i0 = tg / Q;
    int step = (gridDim.x * 256) / Q;
    float4 p = make_float4(0.f, 0.f, 0.f, 0.f);
    for (int i = i0; i < N_ENT; i += step) {
        float4 x = *reinterpret_cast<const float4*>(t + (size_t)i * ST + 4 * q);
        p.x += x.x; p.y += x.y; p.z += x.z; p.w += x.w;
    }
    u64 pr[2] = { pack2(p.x, p.y), pack2(p.z, p.w) };
    warp_reduce2<Q, 2>(pr);
    if ((threadIdx.x & 31) < Q && (threadIdx.x & 31) == (q & 31)) {
        float2 lo = unpack2(pr[0]), hi = unpack2(pr[1]);
        redv4(gsum + 4 * q, make_float4(lo.x, lo.y, hi.x, hi.y));
    }
}

// ------------- layer-1 prep (identity norm) block ---------------------------
DEVFN void prep_ident_block(const float* __restrict__ W, const float* __restrict__ b,
                            const float* __restrict__ gslots,
                            float* Weff, float* constv) {
    __shared__ float sg[16];
    int tid = threadIdx.x;
    if (tid < 16) {
        float s = 0.f;
        for (int k = 0; k < SLOTS; ++k) s += gslots[(size_t)k * 16 + tid];
        sg[tid] = s * INV_NNZ;
    }
    __syncthreads();
    for (int i = tid; i < 2 * 16 * 32; i += 256) Weff[i] = W[i];
    if (tid < 32) {
        float acc = b[tid];
        for (int k = 0; k < 16; ++k) acc += sg[k] * W[6 * 16 * 32 + k * 32 + tid];
        constv[tid] = acc;
    }
}

// ------------- stats + weight fold (layers 2,3) -----------------------------
template<int CIN, int COUT>
__global__ void __launch_bounds__(256)
k_prep(const float* __restrict__ W, const float* __restrict__ b,
       const float* __restrict__ gsum, const float* __restrict__ qslots,
       float* sb, float* tb, float* Weff, float* constv) {
    __shared__ float ssm[CIN], stm[CIN], sgm[CIN];
    int tid = threadIdx.x;
    if (tid < CIN) {
        float sq = 0.f;
        for (int k = 0; k < SLOTS; ++k) sq += qslots[(size_t)k * CIN + tid];
        float sm  = gsum[tid];
        float m   = sm * INV_NNZ;
        float var = sq * INV_NNZ - m * m;
        float sc  = rsqrtf(var + EPSv);
        ssm[tid] = sc; stm[tid] = -m * sc; sgm[tid] = sm;
        sb[tid] = sc; tb[tid] = -m * sc;
    }
    __syncthreads();
    for (int i = tid; i < 2 * CIN * COUT; i += 256) {
        int k = (i % (CIN * COUT)) / COUT;
        Weff[i] = ssm[k] * W[i];
    }
    if (tid < COUT) {
        float acc = b[tid];
        for (int k = 0; k < CIN; ++k) {
            float tk  = stm[k];
            float tmt = fmaf(sgm[k] * INV_NNZ, ssm[k], tk);
            acc += tk * (W[k * COUT + tid] + W[CIN * COUT + k * COUT + tid])
                 + tmt * W[6 * CIN * COUT + k * COUT + tid];
        }
        constv[tid] = acc;
    }
}

// ------------- per-entity A/B precompute into interleaved AB table ----------
template<int CIN, int COUT, bool IDENT>
__global__ void __launch_bounds__(256)
k_entity(const float* __restrict__ rc, const float* __restrict__ cnt,
         const float* __restrict__ sv, const float* __restrict__ tv,
         const float* __restrict__ W, const float* __restrict__ bvec,
         const float* __restrict__ gslots,
         float* __restrict__ AB, float* Weff, float* constv) {
    if (IDENT && blockIdx.x == gridDim.x - 1) {
        prep_ident_block(W, bvec, gslots, Weff, constv);
        return;
    }
    __shared__ __align__(16) float sW[4 * CIN * COUT];
    __shared__ float ss[CIN], st[CIN];
    int tid = threadIdx.x;
    for (int i = tid; i < 4 * CIN * COUT; i += 256) sW[i] = W[2 * CIN * COUT + i];
    if (!IDENT && tid < CIN) { ss[tid] = sv[tid]; st[tid] = tv[tid]; }
    __syncthreads();

    int gid = blockIdx.x * 256 + tid;
    int i = gid >> 1, half = gid & 1;
    if (i >= N_ENT) return;

    float cr = cnt[i];
    float ir = cr > 0.f ? 1.f / cr : 0.f;

    u64 acc[COUT / 2];
#pragma unroll
    for (int q = 0; q < COUT / 2; ++q) acc[q] = 0ull;

    const float* Wa = sW + (size_t)half * CIN * COUT;        // W2 / W3
    const float* Wb = sW + (size_t)(2 + half) * CIN * COUT;  // W4 / W5

    const float4* r4 = reinterpret_cast<const float4*>(rc + (size_t)i * 2 * CIN);
    const float4* c4 = reinterpret_cast<const float4*>(rc + (size_t)i * 2 * CIN + CIN);
    for (int k4 = 0; k4 < CIN / 4; ++k4) {
        float4 rv = r4[k4], cv = c4[k4];
#pragma unroll
        for (int s4 = 0; s4 < 4; ++s4) {
            int k = 4 * k4 + s4;
            float fr, fc;
            if (IDENT) {
                fr = lane4(rv, s4) * ir;
                fc = lane4(cv, s4) * ir;
            } else {
                fr = (cr > 0.f) ? fmaf(lane4(rv, s4) * ir, ss[k], st[k]) : 0.f;
                fc = (cr > 0.f) ? fmaf(lane4(cv, s4) * ir, ss[k], st[k]) : 0.f;
            }
            accum_pair<COUT>(acc, Wa + k * COUT, Wb + k * COUT, fr, fc);
        }
    }
    float* dst = AB + (size_t)i * 2 * COUT + (half ? COUT : 0);
    float4* d4 = reinterpret_cast<float4*>(dst);
#pragma unroll
    for (int q = 0; q < COUT / 4; ++q) {
        float2 lo = unpack2(acc[2 * q]), hi = unpack2(acc[2 * q + 1]);
        d4[q] = make_float4(lo.x, lo.y, hi.x, hi.y);
    }
}

// ------------- main paired per-nnz kernel: CHUNK=4, dense wavefronts --------
template<int CIN, int COUT, bool STORE_O, bool DO_COL>
__global__ void __launch_bounds__(256, 4)
k_mainp(const float* __restrict__ vin, const int* __restrict__ row,
        const int* __restrict__ col,
        const float* __restrict__ Weff, const float* __restrict__ constv,
        const float* __restrict__ AB,
        float* __restrict__ o, float* __restrict__ rc,
        float* __restrict__ qslots) {
    constexpr int CHUNK = 4;
    constexpr int TPP   = COUT / CHUNK;       // 8 or 16
    constexpr int PPB   = 256 / TPP;          // 32 or 16
    constexpr int ITER  = 5;
    constexpr int RST   = DO_COL ? 2 * COUT : COUT;

    __shared__ __align__(16) float sW[2 * CIN * COUT];
    __shared__ float sC[COUT];
    int tid = threadIdx.x;
    for (int i = tid; i < 2 * CIN * COUT; i += 256) sW[i] = Weff[i];
    if (tid < COUT) sC[tid] = constv[tid];
    __syncthreads();

    int ch    = tid % TPP;
    int slotp = tid / TPP;
    int cbase = ch * CHUNK;

    u64 sq[2] = { 0ull, 0ull };

#pragma unroll 1
    for (int it = 0; it < ITER; ++it) {
        int j = (blockIdx.x * ITER + it) * PPB + slotp;   // exact
        int r = row[j], c = col[j];

        const float* abr = AB + (size_t)r * 2 * COUT;
        const float* abc = AB + (size_t)c * 2 * COUT;
        float4 a  = __ldg(reinterpret_cast<const float4*>(abr + cbase));
        float4 b  = __ldg(reinterpret_cast<const float4*>(abc + COUT + cbase));
        float4 a2 = __ldg(reinterpret_cast<const float4*>(abc + cbase));
        float4 b2 = __ldg(reinterpret_cast<const float4*>(abr + COUT + cbase));

        u64 acc0[2], acc1[2];
        acc0[0] = pack2(a.x + b.x + sC[cbase],     a.y + b.y + sC[cbase + 1]);
        acc0[1] = pack2(a.z + b.z + sC[cbase + 2], a.w + b.w + sC[cbase + 3]);
        acc1[0] = pack2(a2.x + b2.x + sC[cbase],     a2.y + b2.y + sC[cbase + 1]);
        acc1[1] = pack2(a2.z + b2.z + sC[cbase + 2], a2.w + b2.w + sC[cbase + 3]);

        const float4* v4 = reinterpret_cast<const float4*>(vin + (size_t)j * CIN);
        const float4* g4 = reinterpret_cast<const float4*>(vin + (size_t)(j + HALFv) * CIN);
#pragma unroll
        for (int k4 = 0; k4 < CIN / 4; ++k4) {
            float4 xv = __ldg(v4 + k4);
            float4 yv = __ldg(g4 + k4);
#pragma unroll
            for (int s4 = 0; s4 < 4; ++s4) {
                int k = 4 * k4 + s4;
                float x = lane4(xv, s4), y = lane4(yv, s4);
                const float* W0 = sW + k * COUT + cbase;
                const float* W1 = sW + CIN * COUT + k * COUT + cbase;
                accum_pair<CHUNK>(acc0, W0, W1, x, y);   // h[j]
                accum_pair<CHUNK>(acc1, W0, W1, y, x);   // h[j+HALF]
            }
        }

        float2 lo0 = unpack2(acc0[0]), hi0 = unpack2(acc0[1]);
        float4 h0 = make_float4(fmaxf(lo0.x, 0.f), fmaxf(lo0.y, 0.f),
                                fmaxf(hi0.x, 0.f), fmaxf(hi0.y, 0.f));
        float2 lo1 = unpack2(acc1[0]), hi1 = unpack2(acc1[1]);
        float4 h1 = make_float4(fmaxf(lo1.x, 0.f), fmaxf(lo1.y, 0.f),
                                fmaxf(hi1.x, 0.f), fmaxf(hi1.y, 0.f));

        if (STORE_O) {
            *reinterpret_cast<float4*>(o + (size_t)j * COUT + cbase) = h0;
            *reinterpret_cast<float4*>(o + (size_t)(j + HALFv) * COUT + cbase) = h1;
        }
        redv4(rc + (size_t)r * RST + cbase, h0);          // rsum[r] += h0
        redv4(rc + (size_t)c * RST + cbase, h1);          // rsum[c] += h1
        if (DO_COL) {
            redv4(rc + (size_t)r * RST + COUT + cbase, h1);   // csum[r] += h1
            redv4(rc + (size_t)c * RST + COUT + cbase, h0);   // csum[c] += h0
        }
        u64 p0 = pack2(h0.x, h0.y), p1 = pack2(h0.z, h0.w);
        u64 p2 = pack2(h1.x, h1.y), p3 = pack2(h1.z, h1.w);
        fma2(sq[0], p0, p0); fma2(sq[1], p1, p1);
        fma2(sq[0], p2, p2); fma2(sq[1], p3, p3);
    }

    warp_reduce2<TPP, 2>(sq);
    if ((tid & 31) < TPP) {
        int slot = ((blockIdx.x * 256 + tid) >> 5) & (SLOTS - 1);
        float2 lo = unpack2(sq[0]), hi = unpack2(sq[1]);
        redv4(qslots + (size_t)slot * COUT + cbase,
              make_float4(lo.x, lo.y, hi.x, hi.y));
    }
}

// ------------- head ---------------------------------------------------------
__global__ void __launch_bounds__(512)
k_prep_head(const float* __restrict__ Wp, const float* __restrict__ bp,
            const float* __restrict__ Wl, const float* __restrict__ bl,
            const float* __restrict__ gsum, const float* __restrict__ qslots,
            float* sb, float* tb, float* G, float* cvec) {
    int tid = threadIdx.x;
    if (tid < 32) {
        float sq = 0.f;
        for (int k = 0; k < SLOTS; ++k) sq += qslots[(size_t)k * 32 + tid];
        float sm  = gsum[tid];
        float m   = sm * INV_NNZ;
        float var = sq * INV_NNZ - m * m;
        float sc  = rsqrtf(var + EPSv);
        sb[tid] = sc;
        tb[tid] = -m * sc;
    }
    if (tid < 32 * 16) {
        int kin = tid >> 4, c = tid & 15;
        float g = 0.f;
        for (int e = 0; e < 16; ++e) g += Wp[kin * 16 + e] * Wl[e * 16 + c];
        G[tid] = g;
    }
    if (tid < 16) {
        float cv = bl[tid];
        for (int e = 0; e < 16; ++e) cv += bp[e] * Wl[e * 16 + tid];
        cvec[tid] = cv;
    }
}

__global__ void __launch_bounds__(256)
k_final(const float* __restrict__ rs, const float* __restrict__ cnt,
        const float* __restrict__ sv, const float* __restrict__ tv,
        const float* __restrict__ G, const float* __restrict__ cvec,
        float* __restrict__ out) {
    __shared__ __align__(16) float sG[32 * 16];
    __shared__ float scv[16], ss[32], st[32];
    int tid = threadIdx.x;
    for (int i = tid; i < 512; i += 256) sG[i] = G[i];
    if (tid < 16) scv[tid] = cvec[tid];
    if (tid < 32) { ss[tid] = sv[tid]; st[tid] = tv[tid]; }
    __syncthreads();

    int i = blockIdx.x * 256 + tid;
    if (i >= N_ENT) return;
    float cr = cnt[i];
    float ir = cr > 0.f ? 1.f / cr : 0.f;

    u64 acc[8];
#pragma unroll
    for (int q = 0; q < 8; ++q) acc[q] = pack2(scv[2 * q], scv[2 * q + 1]);

    const float4* r4 = reinterpret_cast<const float4*>(rs + (size_t)i * 32);
    for (int k4 = 0; k4 < 8; ++k4) {
        float4 rv = r4[k4];
#pragma unroll
        for (int s4 = 0; s4 < 4; ++s4) {
            int k = 4 * k4 + s4;
            float f = (cr > 0.f) ? fmaf(lane4(rv, s4) * ir, ss[k], st[k]) : 0.f;
            accum_one<16>(acc, sG + k * 16, f);
        }
    }
    float4* d4 = reinterpret_cast<float4*>(out + (size_t)i * 16);
#pragma unroll
    for (int q = 0; q < 4; ++q) {
        float2 lo = unpack2(acc[2 * q]), hi = unpack2(acc[2 * q + 1]);
        d4[q] = make_float4(lo.x, lo.y, hi.x, hi.y);
    }
}

// ------------- host orchestration -------------------------------------------
extern "C" void kernel_launch(void* const* d_in, const int* in_sizes, int n_in,
                              void* d_out, int out_size) {
    const float* values = (const float*)d_in[0];
    const int*   row    = (const int*)d_in[1];
    const int*   col    = (const int*)d_in[2];
    const float* W1 = (const float*)d_in[4];  const float* b1 = (const float*)d_in[5];
    const float* W2 = (const float*)d_in[6];  const float* b2 = (const float*)d_in[7];
    const float* W3 = (const float*)d_in[8];  const float* b3 = (const float*)d_in[9];
    const float* Wp = (const float*)d_in[10]; const float* bp = (const float*)d_in[11];
    const float* Wl = (const float*)d_in[12]; const float* bl = (const float*)d_in[13];
    float* out = (float*)d_out;

    float* S = nullptr;
    cudaGetSymbolAddress((void**)&S, g_scratch);

    float *RC0 = S + O_RC0, *RC1 = S + O_RC1, *RC2 = S + O_RC2, *R3 = S + O_R3;
    float *cnt = S + O_CNT, *GS0 = S + O_GS0;
    float *Q1 = S + O_Q1, *Q2 = S + O_Q2, *Q3 = S + O_Q3;
    float *GV1 = S + O_GV1, *GV2 = S + O_GV2, *GV3 = S + O_GV3;
    float *AB = S + O_AB;
    float *o1 = S + O_O1, *o2 = S + O_O2;
    float *sb = S + O_SB, *tb = S + O_TB, *cvv = S + O_CONST, *Weff = S + O_WEFF;
    float *G = S + O_G, *cvec = S + O_CV;

    constexpr int GSI  = HALFv / 64;            // 12500 exact (TPP=4)
    constexpr int GM8  = HALFv / (32 * 5);      // 5000 exact  (TPP=8,  COUT=32)
    constexpr int GM16 = HALFv / (16 * 5);      // 10000 exact (TPP=16, COUT=64)
    constexpr int GE   = (2 * N_ENT + 255) / 256;

    // 1. zero
    k_zero<<<2048, 256>>>((float4*)S, (int)(ZERO_TOTAL / 4));
    // 2. input pass
    k_sum_input<<<GSI, 256>>>(values, row, col, RC0, cnt, GS0);
    // 3. entity1 (+layer-1 prep block)
    k_entity<16, 32, true><<<GE + 1, 256>>>(RC0, cnt, nullptr, nullptr,
                                            W1, b1, GS0, AB, Weff, cvv);
    // 4. main layer 1  <- profiled slot
    k_mainp<16, 32, true, true><<<GM8, 256>>>(values, row, col, Weff, cvv,
                                              AB, o1, RC1, Q1);
    // layer 2
    k_reduce<32, 64><<<64, 256>>>(RC1, GV1);
    k_prep<32, 64><<<1, 256>>>(W2, b2, GV1, Q1, sb, tb, Weff, cvv);
    k_entity<32, 64, false><<<GE, 256>>>(RC1, cnt, sb, tb, W2, b2, nullptr,
                                         AB, Weff, cvv);
    k_mainp<32, 64, true, true><<<GM16, 256>>>(o1, row, col, Weff, cvv,
                                               AB, o2, RC2, Q2);
    // layer 3
    k_reduce<64, 128><<<64, 256>>>(RC2, GV2);
    k_prep<64, 32><<<1, 256>>>(W3, b3, GV2, Q2, sb, tb, Weff, cvv);
    k_entity<64, 32, false><<<GE, 256>>>(RC2, cnt, sb, tb, W3, b3, nullptr,
                                         AB, Weff, cvv);
    k_mainp<64, 32, false, false><<<GM8, 256>>>(o2, row, col, Weff, cvv,
                                                AB, nullptr, R3, Q3);
    // head
    k_reduce<32, 32><<<64, 256>>>(R3, GV3);
    k_prep_head<<<1, 512>>>(Wp, bp, Wl, bl, GV3, Q3, sb, tb, G, cvec);
    k_final<<<(N_ENT + 255) / 256, 256>>>(R3, cnt, sb, tb, G, cvec, out);
}